// round 4
// baseline (speedup 1.0000x reference)
#include <cuda_runtime.h>

// ---------------------------------------------------------------------------
// CoalUMLP block, C=112, spatial 64^3, B=1.
// Pipeline (all stream-ordered, graph-capturable, deterministic):
//   1  stats(x)                       -> n1 stats
//   2  conv1(gn_n1(x))       -> a_pre -> na1 stats
//   3  A = gelu(gn_na1(a_pre))
//   4  branch D/H/W: s (+)= gelu(conv2*(shift(A)))   (W branch -> na2 stats)
//   5  x1 = x + conv3(gn_na2(s)) + h0                 -> n2 stats
//   6  t = gelu(fc1(gn_n2(x1)))
//   7  out = x1 + fc2(t)
// GEMV cores use Blackwell packed fma.rn.f32x2 (2x FP32 FMA rate).
// ---------------------------------------------------------------------------

#define Cc      112
#define NSP     262144           // 64*64*64
#define NTOTAL  (Cc*NSP)         // 29,360,128
#define HID     448
#define NTHR    256
#define NBLK    (NSP/NTHR)       // 1024
#define EPSF    1e-5

// scratch (static device arrays; no allocation allowed)
__device__ float  g_apre[NTOTAL];
__device__ float  g_A[NTOTAL];
__device__ float  g_s[NTOTAL];
__device__ float  g_x1[NTOTAL];
__device__ float  g_t[HID * NSP];
__device__ float2 g_part[NBLK];
__device__ double g_stats[8];    // [0,1]=x  [2,3]=a_pre  [4,5]=s  [6,7]=x1

// ---------------- helpers -------------------------------------------------
__device__ __forceinline__ unsigned long long splat2(float v) {
    unsigned int u = __float_as_uint(v);
    unsigned long long r;
    asm("mov.b64 %0, {%1, %1};" : "=l"(r) : "r"(u));
    return r;
}
__device__ __forceinline__ void fma2(unsigned long long& d,
                                     unsigned long long a,
                                     unsigned long long b) {
    asm("fma.rn.f32x2 %0, %1, %2, %0;" : "+l"(d) : "l"(a), "l"(b));
}
__device__ __forceinline__ float2 unpk(unsigned long long v) {
    unsigned int lo, hi;
    asm("mov.b64 {%0, %1}, %2;" : "=r"(lo), "=r"(hi) : "l"(v));
    return make_float2(__uint_as_float(lo), __uint_as_float(hi));
}
__device__ __forceinline__ float gelu_f(float x) {
    return 0.5f * x * (1.0f + erff(x * 0.70710678118654752440f));
}
// (mu, rsigma) from accumulated double sums
__device__ __forceinline__ float2 gn_musig(int idx) {
    double mu  = g_stats[idx] * (1.0 / (double)NTOTAL);
    double var = g_stats[idx + 1] * (1.0 / (double)NTOTAL) - mu * mu;
    float  rs  = (float)(1.0 / sqrt(var + (double)EPSF));
    return make_float2((float)mu, rs);
}
// deterministic per-block partial (sum, sumsq)
__device__ __forceinline__ void write_partial(float s1, float s2) {
    __shared__ float r1[8], r2[8];
    #pragma unroll
    for (int o = 16; o; o >>= 1) {
        s1 += __shfl_down_sync(0xffffffffu, s1, o);
        s2 += __shfl_down_sync(0xffffffffu, s2, o);
    }
    int wid = threadIdx.x >> 5, lane = threadIdx.x & 31;
    if (!lane) { r1[wid] = s1; r2[wid] = s2; }
    __syncthreads();
    if (threadIdx.x == 0) {
        float a = 0.f, b = 0.f;
        #pragma unroll
        for (int i = 0; i < 8; i++) { a += r1[i]; b += r2[i]; }
        g_part[blockIdx.x] = make_float2(a, b);
    }
}

// ---------------- small kernels -------------------------------------------
__global__ void k_stats(const float* __restrict__ x) {
    float s1 = 0.f, s2 = 0.f;
    for (int i = (blockIdx.x * NTHR + threadIdx.x) * 4; i < NTOTAL;
         i += gridDim.x * NTHR * 4) {
        float4 v = *(const float4*)(x + i);
        s1 += v.x + v.y + v.z + v.w;
        s2 += v.x * v.x + v.y * v.y + v.z * v.z + v.w * v.w;
    }
    write_partial(s1, s2);
}

__global__ void k_reduce(int n, int outIdx) {
    __shared__ double d1[NTHR], d2[NTHR];
    double a = 0.0, b = 0.0;
    for (int i = threadIdx.x; i < n; i += NTHR) {
        a += (double)g_part[i].x;
        b += (double)g_part[i].y;
    }
    d1[threadIdx.x] = a; d2[threadIdx.x] = b;
    __syncthreads();
    for (int s = NTHR / 2; s; s >>= 1) {
        if (threadIdx.x < s) {
            d1[threadIdx.x] += d1[threadIdx.x + s];
            d2[threadIdx.x] += d2[threadIdx.x + s];
        }
        __syncthreads();
    }
    if (!threadIdx.x) { g_stats[outIdx] = d1[0]; g_stats[outIdx + 1] = d2[0]; }
}

// A = gelu(gn_na1(a_pre))
__global__ void k_gngelu(const float* __restrict__ gg, const float* __restrict__ gb) {
    float2 ms = gn_musig(2);
    for (int i = (blockIdx.x * NTHR + threadIdx.x) * 4; i < NTOTAL;
         i += gridDim.x * NTHR * 4) {
        int   c  = i >> 18;          // N = 2^18
        float gv = __ldg(gg + c);
        float sc = ms.y * gv;
        float sh = __ldg(gb + c) - ms.x * sc;
        float4 v = *(const float4*)(g_apre + i);
        v.x = gelu_f(v.x * sc + sh);
        v.y = gelu_f(v.y * sc + sh);
        v.z = gelu_f(v.z * sc + sh);
        v.w = gelu_f(v.w * sc + sh);
        *(float4*)(g_A + i) = v;
    }
}

// ---------------- GEMV macro core ------------------------------------------
// acc[56] packed pairs over 112 output channels; LOADV(k) yields input value.
#define GEMV112_BODY(KDIM, LOADV)                                              \
    unsigned long long acc[56];                                                \
    _Pragma("unroll")                                                          \
    for (int i = 0; i < 56; i++) acc[i] = 0ull;                                \
    {                                                                          \
        float vb[4];                                                           \
        _Pragma("unroll")                                                      \
        for (int i = 0; i < 4; i++) { int k = i; vb[i] = LOADV; }              \
        _Pragma("unroll 1")                                                    \
        for (int k0 = 0; k0 < (KDIM); k0 += 4) {                               \
            float nv[4];                                                       \
            _Pragma("unroll")                                                  \
            for (int i = 0; i < 4; i++) {                                      \
                int k = k0 + 4 + i;                                            \
                nv[i] = (k < (KDIM)) ? (LOADV) : 0.f;                          \
            }                                                                  \
            _Pragma("unroll")                                                  \
            for (int j = 0; j < 4; j++) {                                      \
                int k = k0 + j;                                                \
                unsigned long long vv = splat2(vb[j]);                         \
                const ulonglong2* wr = (const ulonglong2*)(wt + k * Cc);       \
                _Pragma("unroll")                                              \
                for (int i = 0; i < 28; i++) {                                 \
                    ulonglong2 ww = wr[i];                                     \
                    fma2(acc[2 * i], ww.x, vv);                                \
                    fma2(acc[2 * i + 1], ww.y, vv);                            \
                }                                                              \
            }                                                                  \
            _Pragma("unroll")                                                  \
            for (int i = 0; i < 4; i++) vb[i] = nv[i];                         \
        }                                                                      \
    }

// ---------------- conv1: a_pre = W1 @ gn_n1(x) ------------------------------
__global__ void __launch_bounds__(NTHR, 1)
k_conv1(const float* __restrict__ x, const float* __restrict__ w,
        const float* __restrict__ bias, const float* __restrict__ gg,
        const float* __restrict__ gb) {
    extern __shared__ float sm[];
    float* wt  = sm;              // [k][c] transposed, 112*112
    float* isc = sm + Cc * Cc;
    float* ish = isc + Cc;
    float2 ms = gn_musig(0);
    for (int i = threadIdx.x; i < Cc * Cc; i += NTHR) {
        int k = i / Cc, c = i % Cc;
        wt[i] = w[c * Cc + k];
    }
    for (int i = threadIdx.x; i < Cc; i += NTHR) {
        float gv = gg[i];
        isc[i] = ms.y * gv;
        ish[i] = gb[i] - ms.x * ms.y * gv;
    }
    __syncthreads();
    int n = blockIdx.x * NTHR + threadIdx.x;
    const float* xin = x + n;
    GEMV112_BODY(Cc, (__ldg(xin + k * NSP) * isc[k] + ish[k]))
    float s1 = 0.f, s2 = 0.f;
    #pragma unroll
    for (int i = 0; i < 56; i++) {
        float2 f = unpk(acc[i]);
        int c0 = 2 * i;
        float o0 = f.x + __ldg(bias + c0);
        float o1 = f.y + __ldg(bias + c0 + 1);
        g_apre[c0 * NSP + n]       = o0;
        g_apre[(c0 + 1) * NSP + n] = o1;
        s1 += o0 + o1;
        s2 += o0 * o0 + o1 * o1;
    }
    write_partial(s1, s2);
}

// ---------------- axial-shift branches --------------------------------------
// BR=0 (D): src (d-sk, h, w);  BR=1 (H): (d-3, h-sk-3, w-3);
// BR=2 (W): (d-6, h-6, w-sk-6).  sk = k/16 - 3. zeros OOB.
template <int BR>
__global__ void __launch_bounds__(NTHR, 1)
k_branch(const float* __restrict__ w, const float* __restrict__ bias) {
    extern __shared__ float sm[];
    float* wt = sm;
    for (int i = threadIdx.x; i < Cc * Cc; i += NTHR) {
        int k = i / Cc, c = i % Cc;
        wt[i] = w[c * Cc + k];
    }
    __syncthreads();
    int n = blockIdx.x * NTHR + threadIdx.x;
    int d = n >> 12, h = (n >> 6) & 63, wq = n & 63;

    #define SHLOAD                                                              \
        ({ int sk = (k >> 4) - 3; int dd, hh, ww;                               \
           if (BR == 0)      { dd = d - sk; hh = h;          ww = wq; }         \
           else if (BR == 1) { dd = d - 3;  hh = h - sk - 3; ww = wq - 3; }     \
           else              { dd = d - 6;  hh = h - 6;      ww = wq - sk - 6; }\
           bool ok = ((unsigned)dd < 64u) & ((unsigned)hh < 64u) &              \
                     ((unsigned)ww < 64u);                                      \
           ok ? __ldg(g_A + k * NSP + (dd << 12) + (hh << 6) + ww) : 0.f; })

    GEMV112_BODY(Cc, SHLOAD)
    #undef SHLOAD

    float s1 = 0.f, s2 = 0.f;
    #pragma unroll
    for (int i = 0; i < 56; i++) {
        float2 f = unpk(acc[i]);
        int c0 = 2 * i;
        float o0 = gelu_f(f.x + __ldg(bias + c0));
        float o1 = gelu_f(f.y + __ldg(bias + c0 + 1));
        int i0 = c0 * NSP + n, i1 = (c0 + 1) * NSP + n;
        if (BR == 0) {
            g_s[i0] = o0; g_s[i1] = o1;
        } else {
            o0 += g_s[i0]; o1 += g_s[i1];
            g_s[i0] = o0;  g_s[i1] = o1;
            if (BR == 2) { s1 += o0 + o1; s2 += o0 * o0 + o1 * o1; }
        }
    }
    if (BR == 2) write_partial(s1, s2);
}

// ---------------- conv3 + residuals: x1 = x + conv3(gn_na2(s)) + h0 ---------
__global__ void __launch_bounds__(NTHR, 1)
k_conv3(const float* __restrict__ x, const float* __restrict__ w,
        const float* __restrict__ bias, const float* __restrict__ n1g,
        const float* __restrict__ n1b, const float* __restrict__ na2g,
        const float* __restrict__ na2b) {
    extern __shared__ float sm[];
    float* wt  = sm;
    float* isc = sm + Cc * Cc;
    float* ish = isc + Cc;
    float* hsc = ish + Cc;   // h0 = gn_n1(x) affine
    float* hsh = hsc + Cc;
    float2 ms2 = gn_musig(4);   // na2 over s
    float2 ms1 = gn_musig(0);   // n1 over x
    for (int i = threadIdx.x; i < Cc * Cc; i += NTHR) {
        int k = i / Cc, c = i % Cc;
        wt[i] = w[c * Cc + k];
    }
    for (int i = threadIdx.x; i < Cc; i += NTHR) {
        float g2 = na2g[i];
        isc[i] = ms2.y * g2;
        ish[i] = na2b[i] - ms2.x * ms2.y * g2;
        float g1 = n1g[i];
        hsc[i] = ms1.y * g1;
        hsh[i] = n1b[i] - ms1.x * ms1.y * g1;
    }
    __syncthreads();
    int n = blockIdx.x * NTHR + threadIdx.x;
    const float* sin = g_s + n;
    GEMV112_BODY(Cc, (__ldg(sin + k * NSP) * isc[k] + ish[k]))
    float s1 = 0.f, s2 = 0.f;
    #pragma unroll
    for (int i = 0; i < 56; i++) {
        float2 f = unpk(acc[i]);
        int c0 = 2 * i;
        float xv0 = __ldg(x + c0 * NSP + n);
        float xv1 = __ldg(x + (c0 + 1) * NSP + n);
        float o0 = xv0 + (xv0 * hsc[c0] + hsh[c0]) + f.x + __ldg(bias + c0);
        float o1 = xv1 + (xv1 * hsc[c0 + 1] + hsh[c0 + 1]) + f.y + __ldg(bias + c0 + 1);
        g_x1[c0 * NSP + n]       = o0;
        g_x1[(c0 + 1) * NSP + n] = o1;
        s1 += o0 + o1;
        s2 += o0 * o0 + o1 * o1;
    }
    write_partial(s1, s2);
}

// ---------------- MLP -------------------------------------------------------
// t[j] = gelu(fc1[j,:] @ gn_n2(x1)); blockIdx.y selects 112-wide j-chunk
__global__ void __launch_bounds__(NTHR, 1)
k_mlp1(const float* __restrict__ w, const float* __restrict__ bias,
       const float* __restrict__ gg, const float* __restrict__ gb) {
    extern __shared__ float sm[];
    float* wt  = sm;
    float* isc = sm + Cc * Cc;
    float* ish = isc + Cc;
    float2 ms = gn_musig(6);
    int jc = blockIdx.y;                       // 0..3
    for (int i = threadIdx.x; i < Cc * Cc; i += NTHR) {
        int k = i / Cc, jj = i % Cc;
        wt[i] = w[(jc * Cc + jj) * Cc + k];
    }
    for (int i = threadIdx.x; i < Cc; i += NTHR) {
        float gv = gg[i];
        isc[i] = ms.y * gv;
        ish[i] = gb[i] - ms.x * ms.y * gv;
    }
    __syncthreads();
    int n = blockIdx.x * NTHR + threadIdx.x;
    const float* xin = g_x1 + n;
    GEMV112_BODY(Cc, (__ldg(xin + k * NSP) * isc[k] + ish[k]))
    #pragma unroll
    for (int i = 0; i < 56; i++) {
        float2 f = unpk(acc[i]);
        int j0 = jc * Cc + 2 * i;
        g_t[j0 * NSP + n]       = gelu_f(f.x + __ldg(bias + j0));
        g_t[(j0 + 1) * NSP + n] = gelu_f(f.y + __ldg(bias + j0 + 1));
    }
}

// out = x1 + fc2 @ t + b
__global__ void __launch_bounds__(NTHR, 1)
k_mlp2(const float* __restrict__ w, const float* __restrict__ bias,
       float* __restrict__ out) {
    extern __shared__ float sm[];
    float* wt = sm;                             // [j][c], 448*112
    for (int i = threadIdx.x; i < HID * Cc; i += NTHR) {
        int j = i / Cc, c = i % Cc;
        wt[i] = w[c * HID + j];
    }
    __syncthreads();
    int n = blockIdx.x * NTHR + threadIdx.x;
    const float* tin = g_t + n;
    GEMV112_BODY(HID, (__ldg(tin + k * NSP)))
    #pragma unroll
    for (int i = 0; i < 56; i++) {
        float2 f = unpk(acc[i]);
        int c0 = 2 * i;
        out[c0 * NSP + n] =
            __ldg(g_x1 + c0 * NSP + n) + f.x + __ldg(bias + c0);
        out[(c0 + 1) * NSP + n] =
            __ldg(g_x1 + (c0 + 1) * NSP + n) + f.y + __ldg(bias + c0 + 1);
    }
}

// ---------------- launch ----------------------------------------------------
extern "C" void kernel_launch(void* const* d_in, const int* in_sizes, int n_in,
                              void* d_out, int out_size) {
    const float* x        = (const float*)d_in[0];
    const float* conv1_w  = (const float*)d_in[1];
    const float* conv1_b  = (const float*)d_in[2];
    const float* conv2d_w = (const float*)d_in[3];
    const float* conv2d_b = (const float*)d_in[4];
    const float* conv2h_w = (const float*)d_in[5];
    const float* conv2h_b = (const float*)d_in[6];
    const float* conv2w_w = (const float*)d_in[7];
    const float* conv2w_b = (const float*)d_in[8];
    const float* conv3_w  = (const float*)d_in[9];
    const float* conv3_b  = (const float*)d_in[10];
    const float* fc1_w    = (const float*)d_in[11];
    const float* fc1_b    = (const float*)d_in[12];
    const float* fc2_w    = (const float*)d_in[13];
    const float* fc2_b    = (const float*)d_in[14];
    const float* n1_g     = (const float*)d_in[15];
    const float* n1_b     = (const float*)d_in[16];
    const float* na1_g    = (const float*)d_in[17];
    const float* na1_b    = (const float*)d_in[18];
    const float* na2_g    = (const float*)d_in[19];
    const float* na2_b    = (const float*)d_in[20];
    const float* n2_g     = (const float*)d_in[21];
    const float* n2_b     = (const float*)d_in[22];
    float* out = (float*)d_out;

    const size_t smConv = (Cc * Cc + 2 * Cc) * sizeof(float);   // 51,072
    const size_t smC3   = (Cc * Cc + 4 * Cc) * sizeof(float);   // 51,968
    const size_t smBr   = (Cc * Cc) * sizeof(float);            // 50,176
    const size_t smM2   = (HID * Cc) * sizeof(float);           // 200,704

    cudaFuncSetAttribute(k_conv1,     cudaFuncAttributeMaxDynamicSharedMemorySize, (int)smConv);
    cudaFuncSetAttribute(k_branch<0>, cudaFuncAttributeMaxDynamicSharedMemorySize, (int)smBr);
    cudaFuncSetAttribute(k_branch<1>, cudaFuncAttributeMaxDynamicSharedMemorySize, (int)smBr);
    cudaFuncSetAttribute(k_branch<2>, cudaFuncAttributeMaxDynamicSharedMemorySize, (int)smBr);
    cudaFuncSetAttribute(k_conv3,     cudaFuncAttributeMaxDynamicSharedMemorySize, (int)smC3);
    cudaFuncSetAttribute(k_mlp1,      cudaFuncAttributeMaxDynamicSharedMemorySize, (int)smConv);
    cudaFuncSetAttribute(k_mlp2,      cudaFuncAttributeMaxDynamicSharedMemorySize, (int)smM2);

    k_stats<<<NBLK, NTHR>>>(x);
    k_reduce<<<1, NTHR>>>(NBLK, 0);
    k_conv1<<<NBLK, NTHR, smConv>>>(x, conv1_w, conv1_b, n1_g, n1_b);
    k_reduce<<<1, NTHR>>>(NBLK, 2);
    k_gngelu<<<NBLK, NTHR>>>(na1_g, na1_b);
    k_branch<0><<<NBLK, NTHR, smBr>>>(conv2d_w, conv2d_b);
    k_branch<1><<<NBLK, NTHR, smBr>>>(conv2h_w, conv2h_b);
    k_branch<2><<<NBLK, NTHR, smBr>>>(conv2w_w, conv2w_b);
    k_reduce<<<1, NTHR>>>(NBLK, 4);
    k_conv3<<<NBLK, NTHR, smC3>>>(x, conv3_w, conv3_b, n1_g, n1_b, na2_g, na2_b);
    k_reduce<<<1, NTHR>>>(NBLK, 6);
    dim3 gm1(NBLK, 4);
    k_mlp1<<<gm1, NTHR, smConv>>>(fc1_w, fc1_b, n2_g, n2_b);
    k_mlp2<<<NBLK, NTHR, smM2>>>(fc2_w, fc2_b, out);
}

// round 9
// speedup vs baseline: 1.8546x; 1.8546x over previous
#include <cuda_runtime.h>
#include <cuda_bf16.h>
#include <cstdint>

// ---------------------------------------------------------------------------
// CoalUMLP block, C=112, spatial 64^3, B=1 — mma.sync (HMMA bf16) version.
// ptxas target is base sm_103 (no 'a'), so tcgen05 is unavailable; we use
// base-ISA warp-level mma.sync.m16n8k16 bf16 with split-fp32 (3-pass) inputs.
// Pipeline (13 launches, graph-capturable, deterministic):
//   1  stats(x)                        -> n1 stats
//   2  conv1(gn_n1(x))        -> a_pre -> na1 stats          [k_mm<0>]
//   3  A = splitpack(gelu(gn_na1(a_pre)))                    [k_gngelu]
//   4  s (+)= gelu(conv2*(shift_br(A)))  br=D,H,W            [k_mm<1..3>]
//   5  x1 = x + h0 + conv3(gn_na2(s))  -> n2 stats           [k_mm<4>]
//   6  t = splitpack(gelu(fc1(gn_n2(x1))))                   [k_mm<5>]
//   7  out = x1 + fc2(t)                                     [k_mm<6>]
// ---------------------------------------------------------------------------

#define Cc      112
#define NSP     262144           // 64*64*64
#define NTOTAL  (Cc*NSP)
#define HID     448
#define EPSF    1e-5
#define NTILE   256              // spatial points per CTA
#define NT      (NSP/NTILE)      // 1024 tiles
#define NBLK    1024
#define KSTEPS  7                // 112 / 16
#define NTHR    256
#define SROW    240              // smem row stride (bytes), 16B-aligned, conflict-free

// smem byte offsets
#define ISC_OFF 0
#define ISH_OFF 512
#define HSC_OFF 1024
#define HSH_OFF 1536
#define A_H_OFF 2048
#define A_L_OFF (A_H_OFF + Cc*SROW)          // 28928
#define B_H_OFF (A_L_OFF + Cc*SROW)          // 55808
#define B_L_OFF (B_H_OFF + NTILE*SROW)       // 117248
#define SMEM_TOTAL (B_L_OFF + NTILE*SROW)    // 178688

// ---- device scratch (static; no allocation allowed) ------------------------
__device__ float    g_apre[NTOTAL];          // conv1 pre-GN output (fp32)
__device__ uint32_t g_Apair[NTOTAL];         // gelu(gn(a_pre)): bf16 hi | lo<<16
__device__ float    g_s[NTOTAL];             // branch accumulator (fp32)
__device__ float    g_x1[NTOTAL];            // block residual 1 (fp32)
__device__ uint32_t g_tpair[HID * NSP];      // MLP hidden: bf16 hi | lo<<16
__device__ float2   g_part[NBLK];            // per-CTA GN partials
__device__ double   g_stats[8];              // [0,1]=x [2,3]=a_pre [4,5]=s [6,7]=x1

// ---- PTX helpers (base ISA only) -------------------------------------------
__device__ __forceinline__ uint32_t smem_to_u32(const void* p) {
    uint32_t a;
    asm("{ .reg .u64 t; cvta.to.shared.u64 t, %1; cvt.u32.u64 %0, t; }"
        : "=r"(a) : "l"(p));
    return a;
}
__device__ __forceinline__ void ldsm4(uint32_t* r, uint32_t addr) {
    asm volatile("ldmatrix.sync.aligned.m8n8.x4.shared.b16 {%0,%1,%2,%3}, [%4];"
        : "=r"(r[0]), "=r"(r[1]), "=r"(r[2]), "=r"(r[3]) : "r"(addr));
}
__device__ __forceinline__ void mma16816(float* c, const uint32_t* a,
                                         const uint32_t* b) {
    asm volatile("mma.sync.aligned.m16n8k16.row.col.f32.bf16.bf16.f32 "
        "{%0,%1,%2,%3}, {%4,%5,%6,%7}, {%8,%9}, {%0,%1,%2,%3};"
        : "+f"(c[0]), "+f"(c[1]), "+f"(c[2]), "+f"(c[3])
        : "r"(a[0]), "r"(a[1]), "r"(a[2]), "r"(a[3]), "r"(b[0]), "r"(b[1]));
}

// ---- common math helpers ----------------------------------------------------
__device__ __forceinline__ float gelu_f(float x) {
    return 0.5f * x * (1.0f + erff(x * 0.70710678118654752440f));
}
__device__ __forceinline__ float2 gn_musig(int idx) {
    double mu  = g_stats[idx] * (1.0 / (double)NTOTAL);
    double var = g_stats[idx + 1] * (1.0 / (double)NTOTAL) - mu * mu;
    float  rs  = (float)(1.0 / sqrt(var + (double)EPSF));
    return make_float2((float)mu, rs);
}
__device__ __forceinline__ uint32_t pack2(__nv_bfloat16 a, __nv_bfloat16 b) {
    return (uint32_t)__bfloat16_as_ushort(a) |
           ((uint32_t)__bfloat16_as_ushort(b) << 16);
}
__device__ __forceinline__ uint32_t split_pair(float v0, float v1, uint32_t& lo) {
    __nv_bfloat16 h0 = __float2bfloat16(v0), h1 = __float2bfloat16(v1);
    float r0 = v0 - __bfloat162float(h0), r1 = v1 - __bfloat162float(h1);
    lo = pack2(__float2bfloat16(r0), __float2bfloat16(r1));
    return pack2(h0, h1);
}
__device__ __forceinline__ uint32_t splitpack1(float v) {
    __nv_bfloat16 h = __float2bfloat16(v);
    return pack2(h, __float2bfloat16(v - __bfloat162float(h)));
}
__device__ __forceinline__ void write_partial8(float s1, float s2) {
    __shared__ float r1[8], r2[8];
    #pragma unroll
    for (int o = 16; o; o >>= 1) {
        s1 += __shfl_down_sync(0xffffffffu, s1, o);
        s2 += __shfl_down_sync(0xffffffffu, s2, o);
    }
    int wid = threadIdx.x >> 5, lane = threadIdx.x & 31;
    if (!lane) { r1[wid] = s1; r2[wid] = s2; }
    __syncthreads();
    if (!threadIdx.x) {
        float a = 0.f, b = 0.f;
        #pragma unroll
        for (int i = 0; i < 8; i++) { a += r1[i]; b += r2[i]; }
        g_part[blockIdx.x] = make_float2(a, b);
    }
}

// ---- small elementwise kernels ----------------------------------------------
__global__ void k_stats(const float* __restrict__ x) {
    float s1 = 0.f, s2 = 0.f;
    for (int i = (blockIdx.x * NTHR + threadIdx.x) * 4; i < NTOTAL;
         i += gridDim.x * NTHR * 4) {
        float4 v = *(const float4*)(x + i);
        s1 += v.x + v.y + v.z + v.w;
        s2 += v.x * v.x + v.y * v.y + v.z * v.z + v.w * v.w;
    }
    write_partial8(s1, s2);
}
__global__ void k_reduce(int n, int outIdx) {
    __shared__ double d1[NTHR], d2[NTHR];
    double a = 0.0, b = 0.0;
    for (int i = threadIdx.x; i < n; i += NTHR) {
        a += (double)g_part[i].x; b += (double)g_part[i].y;
    }
    d1[threadIdx.x] = a; d2[threadIdx.x] = b;
    __syncthreads();
    for (int s = NTHR / 2; s; s >>= 1) {
        if (threadIdx.x < s) {
            d1[threadIdx.x] += d1[threadIdx.x + s];
            d2[threadIdx.x] += d2[threadIdx.x + s];
        }
        __syncthreads();
    }
    if (!threadIdx.x) { g_stats[outIdx] = d1[0]; g_stats[outIdx + 1] = d2[0]; }
}
// g_Apair = splitpack(gelu(gn_na1(g_apre)))
__global__ void k_gngelu(const float* __restrict__ gg, const float* __restrict__ gb) {
    float2 ms = gn_musig(2);
    for (int i = (blockIdx.x * NTHR + threadIdx.x) * 4; i < NTOTAL;
         i += gridDim.x * NTHR * 4) {
        int   c  = i >> 18;
        float gv = __ldg(gg + c);
        float sc = ms.y * gv;
        float sh = __ldg(gb + c) - ms.x * sc;
        float4 v = *(const float4*)(g_apre + i);
        uint4 o;
        o.x = splitpack1(gelu_f(v.x * sc + sh));
        o.y = splitpack1(gelu_f(v.y * sc + sh));
        o.z = splitpack1(gelu_f(v.z * sc + sh));
        o.w = splitpack1(gelu_f(v.w * sc + sh));
        *(uint4*)(g_Apair + i) = o;
    }
}

// ---- axial-shift gather (bf16 pair) ----------------------------------------
// BR=0 (D): (d-sk,h,w); BR=1 (H): (d-3,h-sk-3,w-3); BR=2 (W): (d-6,h-6,w-sk-6)
template <int BR>
__device__ __forceinline__ uint32_t fetch_shift(int k, int d, int h, int wq) {
    int sk = (k >> 4) - 3, dd, hh, ww;
    if (BR == 0)      { dd = d - sk; hh = h;          ww = wq; }
    else if (BR == 1) { dd = d - 3;  hh = h - sk - 3; ww = wq - 3; }
    else              { dd = d - 6;  hh = h - 6;      ww = wq - sk - 6; }
    bool ok = ((unsigned)dd < 64u) & ((unsigned)hh < 64u) & ((unsigned)ww < 64u);
    return ok ? __ldg(g_Apair + (size_t)k * NSP + (dd << 12) + (hh << 6) + ww) : 0u;
}

// ---- weights -> smem A (hi/lo bf16, row-major, SROW stride) -----------------
__device__ __forceinline__ void load_A(char* smem, const float* __restrict__ wsrc,
                                       int rstride) {
    int t = threadIdx.x;
    if (t < Cc) {
        const float* row = wsrc + (size_t)t * rstride;
        char* ah = smem + A_H_OFF + t * SROW;
        char* al = smem + A_L_OFF + t * SROW;
        #pragma unroll
        for (int i = 0; i < 14; i++) {
            float4 v0 = __ldg((const float4*)(row + i * 8));
            float4 v1 = __ldg((const float4*)(row + i * 8 + 4));
            uint4 hv, lv;
            hv.x = split_pair(v0.x, v0.y, lv.x);
            hv.y = split_pair(v0.z, v0.w, lv.y);
            hv.z = split_pair(v1.x, v1.y, lv.z);
            hv.w = split_pair(v1.z, v1.w, lv.w);
            *(uint4*)(ah + i * 16) = hv;
            *(uint4*)(al + i * 16) = lv;
        }
    }
}

// ---- B^T tile build: [n][k] row-major, hi/lo -------------------------------
// V: 0 conv1(x via src), 1..3 branches(g_Apair), 4 conv3(g_s), 5 mlp1(g_x1),
//    6 mlp2(g_tpair chunk q)
template <int V>
__device__ __forceinline__ void build_B(char* smem, int n0,
                                        const float* __restrict__ src,
                                        const float* isc, const float* ish, int q) {
    int t = threadIdx.x;             // n-row within tile
    int n = n0 + t;
    const float* sp = (V == 4) ? (const float*)g_s
                    : (V == 5) ? (const float*)g_x1 : src;
    int d = 0, h = 0, wq = 0;
    if (V >= 1 && V <= 3) { d = n >> 12; h = (n >> 6) & 63; wq = n & 63; }
    char* bh = smem + B_H_OFF + t * SROW;
    char* bl = smem + B_L_OFF + t * SROW;
    #pragma unroll 1
    for (int k0 = 0; k0 < Cc; k0 += 8) {
        uint32_t hv[4], lv[4];
        #pragma unroll
        for (int i = 0; i < 4; i++) {
            int k = k0 + 2 * i;
            if (V == 0 || V == 4 || V == 5) {
                float v0 = __ldg(sp + (size_t)k * NSP + n) * isc[k] + ish[k];
                float v1 = __ldg(sp + (size_t)(k + 1) * NSP + n) * isc[k + 1] + ish[k + 1];
                hv[i] = split_pair(v0, v1, lv[i]);
            } else if (V == 6) {
                uint32_t p0 = __ldg(g_tpair + (size_t)(q * Cc + k) * NSP + n);
                uint32_t p1 = __ldg(g_tpair + (size_t)(q * Cc + k + 1) * NSP + n);
                hv[i] = (p0 & 0xffffu) | (p1 << 16);
                lv[i] = (p0 >> 16) | (p1 & 0xffff0000u);
            } else {
                uint32_t p0 = fetch_shift<V - 1>(k, d, h, wq);
                uint32_t p1 = fetch_shift<V - 1>(k + 1, d, h, wq);
                hv[i] = (p0 & 0xffffu) | (p1 << 16);
                lv[i] = (p0 >> 16) | (p1 & 0xffff0000u);
            }
        }
        *(uint4*)(bh + k0 * 2) = make_uint4(hv[0], hv[1], hv[2], hv[3]);
        *(uint4*)(bl + k0 * 2) = make_uint4(lv[0], lv[1], lv[2], lv[3]);
    }
}

// ---- MMA mainloop: acc[7][4][4] += 3-pass split product --------------------
__device__ __forceinline__ void mma_tile(float (*acc)[4][4], uint32_t sb) {
    int lane = threadIdx.x & 31;
    int nbase = (threadIdx.x >> 5) * 32;
    uint32_t aAddr = sb + A_H_OFF + (uint32_t)(lane & 15) * SROW
                     + (uint32_t)(lane >> 4) * 16;
    uint32_t bRow = (uint32_t)(nbase + ((lane >> 4) << 3) + (lane & 7)) * SROW
                    + (uint32_t)((lane >> 3) & 1) * 16;
    #pragma unroll
    for (int ks = 0; ks < KSTEPS; ks++) {
        uint32_t bh0[4], bh1[4], bl0[4], bl1[4];
        ldsm4(bh0, sb + B_H_OFF + bRow + ks * 32);
        ldsm4(bh1, sb + B_H_OFF + bRow + 16 * SROW + ks * 32);
        ldsm4(bl0, sb + B_L_OFF + bRow + ks * 32);
        ldsm4(bl1, sb + B_L_OFF + bRow + 16 * SROW + ks * 32);
        #pragma unroll
        for (int mt = 0; mt < 7; mt++) {
            uint32_t ah[4], al[4];
            ldsm4(ah, aAddr + mt * 16 * SROW + ks * 32);
            ldsm4(al, aAddr + (A_L_OFF - A_H_OFF) + mt * 16 * SROW + ks * 32);
            #pragma unroll
            for (int nt = 0; nt < 4; nt++) {
                const uint32_t* bhp = (nt < 2) ? bh0 : bh1;
                const uint32_t* blp = (nt < 2) ? bl0 : bl1;
                int p = 2 * (nt & 1);
                mma16816(acc[mt][nt], ah, bhp + p);   // hi*hi
                mma16816(acc[mt][nt], ah, blp + p);   // hi*lo
                mma16816(acc[mt][nt], al, bhp + p);   // lo*hi
            }
        }
    }
}

// ---- main GEMM kernel -------------------------------------------------------
template <int V>
__global__ void __launch_bounds__(NTHR)
k_mm(const float* __restrict__ w, const float* __restrict__ bias,
     const float* __restrict__ src, const float* __restrict__ gg,
     const float* __restrict__ gb, const float* __restrict__ xres,
     const float* __restrict__ n1g, const float* __restrict__ n1b,
     float* __restrict__ dst) {
    extern __shared__ char smem[];
    uint32_t sb = smem_to_u32(smem);
    float* isc = (float*)(smem + ISC_OFF);
    float* ish = (float*)(smem + ISH_OFF);
    float* hsc = (float*)(smem + HSC_OFF);
    float* hsh = (float*)(smem + HSH_OFF);
    int tid = threadIdx.x, lane = tid & 31;
    int n0 = blockIdx.x * NTILE;
    int nbase = (tid >> 5) * 32;

    if (V == 0 || V == 4 || V == 5) {
        float2 ms = gn_musig(V == 0 ? 0 : (V == 4 ? 4 : 6));
        for (int i = tid; i < Cc; i += NTHR) {
            float g = __ldg(gg + i);
            isc[i] = ms.y * g;
            ish[i] = __ldg(gb + i) - ms.x * ms.y * g;
        }
    }
    if (V == 4) {
        float2 m1 = gn_musig(0);
        for (int i = tid; i < Cc; i += NTHR) {
            float g1 = __ldg(n1g + i);
            hsc[i] = m1.y * g1;
            hsh[i] = __ldg(n1b + i) - m1.x * m1.y * g1;
        }
    }
    if (V == 0 || V == 4 || V == 5) __syncthreads();

    float acc[7][4][4];
    #pragma unroll
    for (int a = 0; a < 7; a++)
        #pragma unroll
        for (int b = 0; b < 4; b++)
            #pragma unroll
            for (int u = 0; u < 4; u++) acc[a][b][u] = 0.f;

    int r0 = lane >> 2, cc0 = (lane & 3) * 2;

    if constexpr (V <= 4) {
        build_B<V>(smem, n0, src, isc, ish, 0);
        load_A(smem, w, Cc);
        __syncthreads();
        mma_tile(acc, sb);

        float s1 = 0.f, s2 = 0.f;
        #pragma unroll
        for (int mt = 0; mt < 7; mt++) {
            #pragma unroll
            for (int half = 0; half < 2; half++) {
                int m = mt * 16 + r0 + half * 8;
                float bia = __ldg(bias + m);
                float hc = (V == 4) ? hsc[m] : 0.f;
                float hb = (V == 4) ? hsh[m] : 0.f;
                #pragma unroll
                for (int nt = 0; nt < 4; nt++) {
                    size_t gi = (size_t)m * NSP + n0 + nbase + nt * 8 + cc0;
                    float v0 = acc[mt][nt][2 * half]     + bia;
                    float v1 = acc[mt][nt][2 * half + 1] + bia;
                    float o0, o1;
                    if (V == 0)      { o0 = v0; o1 = v1; }
                    else if (V <= 3) { o0 = gelu_f(v0); o1 = gelu_f(v1); }
                    else {
                        float2 xv = *(const float2*)(xres + gi);
                        o0 = xv.x + (xv.x * hc + hb) + v0;
                        o1 = xv.y + (xv.y * hc + hb) + v1;
                    }
                    if (V == 2 || V == 3) {
                        float2 old = *(const float2*)(g_s + gi);
                        o0 += old.x; o1 += old.y;
                    }
                    float2 ov = make_float2(o0, o1);
                    if (V == 0)      *(float2*)(g_apre + gi) = ov;
                    else if (V <= 3) *(float2*)(g_s + gi) = ov;
                    else             *(float2*)(g_x1 + gi) = ov;
                    if (V == 0 || V == 3 || V == 4) {
                        s1 += o0 + o1; s2 += o0 * o0 + o1 * o1;
                    }
                }
            }
        }
        if (V == 0 || V == 3 || V == 4) write_partial8(s1, s2);
    } else if constexpr (V == 5) {
        build_B<5>(smem, n0, src, isc, ish, 0);
        __syncthreads();
        #pragma unroll 1
        for (int jc = 0; jc < 4; jc++) {
            load_A(smem, w + (size_t)jc * Cc * Cc, Cc);
            __syncthreads();
            #pragma unroll
            for (int a = 0; a < 7; a++)
                #pragma unroll
                for (int b = 0; b < 4; b++)
                    #pragma unroll
                    for (int u = 0; u < 4; u++) acc[a][b][u] = 0.f;
            mma_tile(acc, sb);
            #pragma unroll
            for (int mt = 0; mt < 7; mt++) {
                #pragma unroll
                for (int half = 0; half < 2; half++) {
                    int m = mt * 16 + r0 + half * 8;
                    float bia = __ldg(bias + jc * Cc + m);
                    #pragma unroll
                    for (int nt = 0; nt < 4; nt++) {
                        size_t gi = (size_t)(jc * Cc + m) * NSP + n0 + nbase + nt * 8 + cc0;
                        uint2 pk;
                        pk.x = splitpack1(gelu_f(acc[mt][nt][2 * half]     + bia));
                        pk.y = splitpack1(gelu_f(acc[mt][nt][2 * half + 1] + bia));
                        *(uint2*)(g_tpair + gi) = pk;
                    }
                }
            }
            __syncthreads();
        }
    } else {  // V == 6: out = x1 + fc2 @ t + b  (K=448 as 4 chunks, acc in regs)
        #pragma unroll 1
        for (int q = 0; q < 4; q++) {
            if (q) __syncthreads();
            build_B<6>(smem, n0, nullptr, isc, ish, q);
            load_A(smem, w + q * Cc, HID);
            __syncthreads();
            mma_tile(acc, sb);
        }
        #pragma unroll
        for (int mt = 0; mt < 7; mt++) {
            #pragma unroll
            for (int half = 0; half < 2; half++) {
                int m = mt * 16 + r0 + half * 8;
                float bia = __ldg(bias + m);
                #pragma unroll
                for (int nt = 0; nt < 4; nt++) {
                    size_t gi = (size_t)m * NSP + n0 + nbase + nt * 8 + cc0;
                    float2 xv = *(const float2*)(g_x1 + gi);
                    float2 ov;
                    ov.x = xv.x + acc[mt][nt][2 * half]     + bia;
                    ov.y = xv.y + acc[mt][nt][2 * half + 1] + bia;
                    *(float2*)(dst + gi) = ov;
                }
            }
        }
    }
}

// ---------------- launch -----------------------------------------------------
extern "C" void kernel_launch(void* const* d_in, const int* in_sizes, int n_in,
                              void* d_out, int out_size) {
    const float* x        = (const float*)d_in[0];
    const float* conv1_w  = (const float*)d_in[1];
    const float* conv1_b  = (const float*)d_in[2];
    const float* conv2d_w = (const float*)d_in[3];
    const float* conv2d_b = (const float*)d_in[4];
    const float* conv2h_w = (const float*)d_in[5];
    const float* conv2h_b = (const float*)d_in[6];
    const float* conv2w_w = (const float*)d_in[7];
    const float* conv2w_b = (const float*)d_in[8];
    const float* conv3_w  = (const float*)d_in[9];
    const float* conv3_b  = (const float*)d_in[10];
    const float* fc1_w    = (const float*)d_in[11];
    const float* fc1_b    = (const float*)d_in[12];
    const float* fc2_w    = (const float*)d_in[13];
    const float* fc2_b    = (const float*)d_in[14];
    const float* n1_g     = (const float*)d_in[15];
    const float* n1_b     = (const float*)d_in[16];
    const float* na1_g    = (const float*)d_in[17];
    const float* na1_b    = (const float*)d_in[18];
    const float* na2_g    = (const float*)d_in[19];
    const float* na2_b    = (const float*)d_in[20];
    const float* n2_g     = (const float*)d_in[21];
    const float* n2_b     = (const float*)d_in[22];
    float* out = (float*)d_out;

    cudaFuncSetAttribute(k_mm<0>, cudaFuncAttributeMaxDynamicSharedMemorySize, SMEM_TOTAL);
    cudaFuncSetAttribute(k_mm<1>, cudaFuncAttributeMaxDynamicSharedMemorySize, SMEM_TOTAL);
    cudaFuncSetAttribute(k_mm<2>, cudaFuncAttributeMaxDynamicSharedMemorySize, SMEM_TOTAL);
    cudaFuncSetAttribute(k_mm<3>, cudaFuncAttributeMaxDynamicSharedMemorySize, SMEM_TOTAL);
    cudaFuncSetAttribute(k_mm<4>, cudaFuncAttributeMaxDynamicSharedMemorySize, SMEM_TOTAL);
    cudaFuncSetAttribute(k_mm<5>, cudaFuncAttributeMaxDynamicSharedMemorySize, SMEM_TOTAL);
    cudaFuncSetAttribute(k_mm<6>, cudaFuncAttributeMaxDynamicSharedMemorySize, SMEM_TOTAL);

    // 1. n1 stats on x
    k_stats<<<NBLK, NTHR>>>(x);
    k_reduce<<<1, NTHR>>>(NBLK, 0);
    // 2. conv1 -> a_pre (+ na1 partials)
    k_mm<0><<<NT, NTHR, SMEM_TOTAL>>>(conv1_w, conv1_b, x, n1_g, n1_b,
                                      nullptr, nullptr, nullptr, nullptr);
    k_reduce<<<1, NTHR>>>(NT, 2);
    // 3. A = splitpack(gelu(gn(a_pre)))
    k_gngelu<<<NBLK, NTHR>>>(na1_g, na1_b);
    // 4. branches D, H, W
    k_mm<1><<<NT, NTHR, SMEM_TOTAL>>>(conv2d_w, conv2d_b, nullptr, nullptr, nullptr,
                                      nullptr, nullptr, nullptr, nullptr);
    k_mm<2><<<NT, NTHR, SMEM_TOTAL>>>(conv2h_w, conv2h_b, nullptr, nullptr, nullptr,
                                      nullptr, nullptr, nullptr, nullptr);
    k_mm<3><<<NT, NTHR, SMEM_TOTAL>>>(conv2w_w, conv2w_b, nullptr, nullptr, nullptr,
                                      nullptr, nullptr, nullptr, nullptr);
    k_reduce<<<1, NTHR>>>(NT, 4);
    // 5. conv3 + residuals -> x1 (+ n2 partials)
    k_mm<4><<<NT, NTHR, SMEM_TOTAL>>>(conv3_w, conv3_b, nullptr, na2_g, na2_b,
                                      x, n1_g, n1_b, nullptr);
    k_reduce<<<1, NTHR>>>(NT, 6);
    // 6. MLP
    k_mm<5><<<NT, NTHR, SMEM_TOTAL>>>(fc1_w, fc1_b, nullptr, n2_g, n2_b,
                                      nullptr, nullptr, nullptr, nullptr);
    k_mm<6><<<NT, NTHR, SMEM_TOTAL>>>(fc2_w, fc2_b, nullptr, nullptr, nullptr,
                                      nullptr, nullptr, nullptr, out);
}

// round 11
// speedup vs baseline: 2.0366x; 1.0982x over previous
#include <cuda_runtime.h>
#include <cuda_bf16.h>
#include <cstdint>

// ---------------------------------------------------------------------------
// CoalUMLP block, C=112, 64^3, B=1 — HMMA bf16 split-fp32, fused-phase version.
//   R9 -> R10 changes: 3 branch GEMMs fused (sum in regs, 1 g_s write);
//   mlp1+mlp2 fused via smem t-buffer (g_tpair eliminated); N-tile 128 with
//   SROW=224 -> conv kernels 108KB smem, 2 CTA/SM; GN affine folded into
//   weights/bias for conv1/conv3/fc1.
// Pipeline (10 launches):
//   k_stats/k_reduce -> n1 stats
//   k_conv1: a_pre = conv1_gn(x)            -> na1 partials
//   k_gngelu: Apair = splitpack(gelu(gn(a_pre)))
//   k_branch: s = sum_br gelu(conv2br(shift_br(A)))  -> na2 partials
//   k_conv3: x1 = x + h0 + conv3_gn(s)      -> n2 partials
//   k_mlp:   out = x1 + fc2(gelu(fc1_gn(x1)))
// ---------------------------------------------------------------------------

#define Cc      112
#define NSP     262144
#define NTOTAL  (Cc*NSP)
#define HID     448
#define EPSF    1e-5
#define NTILE   128
#define NT2     (NSP/NTILE)          // 2048
#define KSTEPS  7
#define NTHR    256
#define SROW    224                  // 112 bf16 = 224B rows; 56-bank stride, LDSM-conflict-free

// smem byte offsets
#define ISC_OFF 0
#define ISH_OFF 512
#define FB0_OFF 1024
#define FB1_OFF 1536
#define HSC_OFF 2048
#define HSH_OFF 2560
#define A_H_OFF 3072
#define A_L_OFF (A_H_OFF + Cc*SROW)      // 28160
#define B_H_OFF (A_L_OFF + Cc*SROW)      // 53248
#define B_L_OFF (B_H_OFF + NTILE*SROW)   // 81920
#define SM_CONV (B_L_OFF + NTILE*SROW)   // 110592 (108KB) -> 2 CTA/SM
#define B2_H_OFF SM_CONV                 // 110592 (mlp only)
#define B2_L_OFF (B2_H_OFF + NTILE*SROW) // 139264
#define SM_MLP  (B2_L_OFF + NTILE*SROW)  // 167936 (164KB) -> 1 CTA/SM

// ---- device scratch ---------------------------------------------------------
__device__ float    g_apre[NTOTAL];
__device__ uint32_t g_Apair[NTOTAL];     // bf16 hi | lo<<16
__device__ float    g_s[NTOTAL];
__device__ float    g_x1[NTOTAL];
__device__ float2   g_part[NT2];
__device__ double   g_stats[8];          // [0,1]=x [2,3]=a_pre [4,5]=s [6,7]=x1

// ---- PTX helpers ------------------------------------------------------------
__device__ __forceinline__ uint32_t smem_to_u32(const void* p) {
    uint32_t a;
    asm("{ .reg .u64 t; cvta.to.shared.u64 t, %1; cvt.u32.u64 %0, t; }"
        : "=r"(a) : "l"(p));
    return a;
}
__device__ __forceinline__ void ldsm4(uint32_t* r, uint32_t addr) {
    asm volatile("ldmatrix.sync.aligned.m8n8.x4.shared.b16 {%0,%1,%2,%3}, [%4];"
        : "=r"(r[0]), "=r"(r[1]), "=r"(r[2]), "=r"(r[3]) : "r"(addr));
}
__device__ __forceinline__ void mma16816(float* c, const uint32_t* a,
                                         const uint32_t* b) {
    asm volatile("mma.sync.aligned.m16n8k16.row.col.f32.bf16.bf16.f32 "
        "{%0,%1,%2,%3}, {%4,%5,%6,%7}, {%8,%9}, {%0,%1,%2,%3};"
        : "+f"(c[0]), "+f"(c[1]), "+f"(c[2]), "+f"(c[3])
        : "r"(a[0]), "r"(a[1]), "r"(a[2]), "r"(a[3]), "r"(b[0]), "r"(b[1]));
}

// ---- math helpers -----------------------------------------------------------
__device__ __forceinline__ float gelu_f(float x) {
    return 0.5f * x * (1.0f + erff(x * 0.70710678118654752440f));
}
__device__ __forceinline__ float2 gn_musig(int idx) {
    double mu  = g_stats[idx] * (1.0 / (double)NTOTAL);
    double var = g_stats[idx + 1] * (1.0 / (double)NTOTAL) - mu * mu;
    float  rs  = (float)(1.0 / sqrt(var + (double)EPSF));
    return make_float2((float)mu, rs);
}
__device__ __forceinline__ uint32_t pack2(__nv_bfloat16 a, __nv_bfloat16 b) {
    return (uint32_t)__bfloat16_as_ushort(a) |
           ((uint32_t)__bfloat16_as_ushort(b) << 16);
}
__device__ __forceinline__ uint32_t split_pair(float v0, float v1, uint32_t& lo) {
    __nv_bfloat16 h0 = __float2bfloat16(v0), h1 = __float2bfloat16(v1);
    float r0 = v0 - __bfloat162float(h0), r1 = v1 - __bfloat162float(h1);
    lo = pack2(__float2bfloat16(r0), __float2bfloat16(r1));
    return pack2(h0, h1);
}
__device__ __forceinline__ uint32_t splitpack1(float v) {
    __nv_bfloat16 h = __float2bfloat16(v);
    return pack2(h, __float2bfloat16(v - __bfloat162float(h)));
}
__device__ __forceinline__ void write_partial8(float s1, float s2) {
    __shared__ float r1[8], r2[8];
    #pragma unroll
    for (int o = 16; o; o >>= 1) {
        s1 += __shfl_down_sync(0xffffffffu, s1, o);
        s2 += __shfl_down_sync(0xffffffffu, s2, o);
    }
    int wid = threadIdx.x >> 5, lane = threadIdx.x & 31;
    if (!lane) { r1[wid] = s1; r2[wid] = s2; }
    __syncthreads();
    if (!threadIdx.x) {
        float a = 0.f, b = 0.f;
        #pragma unroll
        for (int i = 0; i < 8; i++) { a += r1[i]; b += r2[i]; }
        g_part[blockIdx.x] = make_float2(a, b);
    }
}

// ---- small elementwise kernels ---------------------------------------------
__global__ void k_stats(const float* __restrict__ x) {
    float s1 = 0.f, s2 = 0.f;
    for (int i = (blockIdx.x * NTHR + threadIdx.x) * 4; i < NTOTAL;
         i += gridDim.x * NTHR * 4) {
        float4 v = *(const float4*)(x + i);
        s1 += v.x + v.y + v.z + v.w;
        s2 += v.x * v.x + v.y * v.y + v.z * v.z + v.w * v.w;
    }
    write_partial8(s1, s2);
}
__global__ void k_reduce(int n, int outIdx) {
    __shared__ double d1[NTHR], d2[NTHR];
    double a = 0.0, b = 0.0;
    for (int i = threadIdx.x; i < n; i += NTHR) {
        a += (double)g_part[i].x; b += (double)g_part[i].y;
    }
    d1[threadIdx.x] = a; d2[threadIdx.x] = b;
    __syncthreads();
    for (int s = NTHR / 2; s; s >>= 1) {
        if (threadIdx.x < s) {
            d1[threadIdx.x] += d1[threadIdx.x + s];
            d2[threadIdx.x] += d2[threadIdx.x + s];
        }
        __syncthreads();
    }
    if (!threadIdx.x) { g_stats[outIdx] = d1[0]; g_stats[outIdx + 1] = d2[0]; }
}
__global__ void k_gngelu(const float* __restrict__ gg, const float* __restrict__ gb) {
    float2 ms = gn_musig(2);
    for (int i = (blockIdx.x * NTHR + threadIdx.x) * 4; i < NTOTAL;
         i += gridDim.x * NTHR * 4) {
        int   c  = i >> 18;
        float gv = __ldg(gg + c);
        float sc = ms.y * gv;
        float sh = __ldg(gb + c) - ms.x * sc;
        float4 v = *(const float4*)(g_apre + i);
        uint4 o;
        o.x = splitpack1(gelu_f(v.x * sc + sh));
        o.y = splitpack1(gelu_f(v.y * sc + sh));
        o.z = splitpack1(gelu_f(v.z * sc + sh));
        o.w = splitpack1(gelu_f(v.w * sc + sh));
        *(uint4*)(g_Apair + i) = o;
    }
}

// ---- axial-shift gather -----------------------------------------------------
template <int BR>
__device__ __forceinline__ uint32_t fetch_shift(int k, int d, int h, int wq) {
    int sk = (k >> 4) - 3, dd, hh, ww;
    if (BR == 0)      { dd = d - sk; hh = h;          ww = wq; }
    else if (BR == 1) { dd = d - 3;  hh = h - sk - 3; ww = wq - 3; }
    else              { dd = d - 6;  hh = h - 6;      ww = wq - sk - 6; }
    bool ok = ((unsigned)dd < 64u) & ((unsigned)hh < 64u) & ((unsigned)ww < 64u);
    return ok ? __ldg(g_Apair + (size_t)k * NSP + (dd << 12) + (hh << 6) + ww) : 0u;
}

// ---- B tile build: raw fp32 source, split-pack ------------------------------
// 256 threads: t&127 = n-row, t>>7 = k-half (56 k's each)
__device__ __forceinline__ void build_dense(char* smem, int n0,
                                            const float* __restrict__ sp) {
    int t7 = threadIdx.x & 127, kh = threadIdx.x >> 7;
    int n = n0 + t7;
    char* bh = smem + B_H_OFF + t7 * SROW;
    char* bl = smem + B_L_OFF + t7 * SROW;
    #pragma unroll 1
    for (int i = 0; i < 7; i++) {
        int k0 = kh * 56 + i * 8;
        uint32_t hv[4], lv[4];
        #pragma unroll
        for (int j = 0; j < 4; j++) {
            int k = k0 + 2 * j;
            float v0 = __ldg(sp + (size_t)k * NSP + n);
            float v1 = __ldg(sp + (size_t)(k + 1) * NSP + n);
            hv[j] = split_pair(v0, v1, lv[j]);
        }
        *(uint4*)(bh + 2 * k0) = make_uint4(hv[0], hv[1], hv[2], hv[3]);
        *(uint4*)(bl + 2 * k0) = make_uint4(lv[0], lv[1], lv[2], lv[3]);
    }
}
// branch source: g_Apair with shift
template <int BR>
__device__ __forceinline__ void build_shift(char* smem, int n0) {
    int t7 = threadIdx.x & 127, kh = threadIdx.x >> 7;
    int n = n0 + t7;
    int d = n >> 12, h = (n >> 6) & 63, wq = n & 63;
    char* bh = smem + B_H_OFF + t7 * SROW;
    char* bl = smem + B_L_OFF + t7 * SROW;
    #pragma unroll 1
    for (int i = 0; i < 7; i++) {
        int k0 = kh * 56 + i * 8;
        uint32_t hv[4], lv[4];
        #pragma unroll
        for (int j = 0; j < 4; j++) {
            int k = k0 + 2 * j;
            uint32_t p0 = fetch_shift<BR>(k, d, h, wq);
            uint32_t p1 = fetch_shift<BR>(k + 1, d, h, wq);
            hv[j] = (p0 & 0xffffu) | (p1 << 16);
            lv[j] = (p0 >> 16) | (p1 & 0xffff0000u);
        }
        *(uint4*)(bh + 2 * k0) = make_uint4(hv[0], hv[1], hv[2], hv[3]);
        *(uint4*)(bl + 2 * k0) = make_uint4(lv[0], lv[1], lv[2], lv[3]);
    }
}

// ---- weights -> smem A (optionally GN-folded: A'=W*isc, fb=sum W*ish) ------
// 224 threads: t>>1 = row, t&1 = k-half
template <bool FOLD>
__device__ __forceinline__ void load_A(char* smem, const float* __restrict__ wsrc,
                                       int rstride) {
    int t = threadIdx.x;
    if (t < 224) {
        int r = t >> 1, h = t & 1;
        const float* row = wsrc + (size_t)r * rstride + h * 56;
        const float* isc = (const float*)(smem + ISC_OFF);
        const float* ish = (const float*)(smem + ISH_OFF);
        char* ah = smem + A_H_OFF + r * SROW + h * 112;
        char* al = smem + A_L_OFF + r * SROW + h * 112;
        float part = 0.f;
        #pragma unroll
        for (int i = 0; i < 7; i++) {
            int kb = h * 56 + i * 8;
            float4 v0 = __ldg((const float4*)(row + i * 8));
            float4 v1 = __ldg((const float4*)(row + i * 8 + 4));
            if (FOLD) {
                part += v0.x * ish[kb] + v0.y * ish[kb + 1] + v0.z * ish[kb + 2]
                      + v0.w * ish[kb + 3] + v1.x * ish[kb + 4] + v1.y * ish[kb + 5]
                      + v1.z * ish[kb + 6] + v1.w * ish[kb + 7];
                v0.x *= isc[kb];     v0.y *= isc[kb + 1];
                v0.z *= isc[kb + 2]; v0.w *= isc[kb + 3];
                v1.x *= isc[kb + 4]; v1.y *= isc[kb + 5];
                v1.z *= isc[kb + 6]; v1.w *= isc[kb + 7];
            }
            uint4 hv, lv;
            hv.x = split_pair(v0.x, v0.y, lv.x);
            hv.y = split_pair(v0.z, v0.w, lv.y);
            hv.z = split_pair(v1.x, v1.y, lv.z);
            hv.w = split_pair(v1.z, v1.w, lv.w);
            *(uint4*)(ah + i * 16) = hv;
            *(uint4*)(al + i * 16) = lv;
        }
        if (FOLD)
            ((float*)(smem + (h ? FB1_OFF : FB0_OFF)))[r] = part;
    }
}

// ---- GN affine setup into smem ---------------------------------------------
__device__ __forceinline__ void setup_affine(char* smem, int statIdx,
                                             const float* gg, const float* gb,
                                             int scOff, int shOff) {
    float2 ms = gn_musig(statIdx);
    for (int i = threadIdx.x; i < Cc; i += NTHR) {
        float g = __ldg(gg + i);
        ((float*)(smem + scOff))[i] = ms.y * g;
        ((float*)(smem + shOff))[i] = __ldg(gb + i) - ms.x * ms.y * g;
    }
}

// ---- MMA mainloop: acc[7][2][4] += 3-pass split product --------------------
__device__ __forceinline__ void mma_tile(float acc[7][2][4], uint32_t sb,
                                         uint32_t bHoff) {
    int lane = threadIdx.x & 31;
    int nbase = (threadIdx.x >> 5) * 16;
    uint32_t aAddr = sb + A_H_OFF + (uint32_t)(lane & 15) * SROW
                     + (uint32_t)(lane >> 4) * 16;
    uint32_t bAddr = sb + bHoff
                   + (uint32_t)(nbase + ((lane >> 4) << 3) + (lane & 7)) * SROW
                   + (uint32_t)((lane >> 3) & 1) * 16;
    const uint32_t dA = A_L_OFF - A_H_OFF;
    const uint32_t dB = NTILE * SROW;      // B_L - B_H
    #pragma unroll
    for (int ks = 0; ks < KSTEPS; ks++) {
        uint32_t bh[4], bl[4];
        ldsm4(bh, bAddr + ks * 32);
        ldsm4(bl, bAddr + dB + ks * 32);
        #pragma unroll
        for (int mt = 0; mt < 7; mt++) {
            uint32_t ah[4], al[4];
            ldsm4(ah, aAddr + mt * 16 * SROW + ks * 32);
            ldsm4(al, aAddr + dA + mt * 16 * SROW + ks * 32);
            #pragma unroll
            for (int nt = 0; nt < 2; nt++) {
                mma16816(acc[mt][nt], ah, bh + 2 * nt);
                mma16816(acc[mt][nt], ah, bl + 2 * nt);
                mma16816(acc[mt][nt], al, bh + 2 * nt);
            }
        }
    }
}
__device__ __forceinline__ void zero_acc(float acc[7][2][4]) {
    #pragma unroll
    for (int a = 0; a < 7; a++)
        #pragma unroll
        for (int b = 0; b < 2; b++)
            #pragma unroll
            for (int u = 0; u < 4; u++) acc[a][b][u] = 0.f;
}

// ---- conv1: a_pre = conv1_gn(x) + b'  (+ na1 partials) ----------------------
__global__ void __launch_bounds__(NTHR, 2)
k_conv1(const float* __restrict__ w, const float* __restrict__ bias,
        const float* __restrict__ x, const float* __restrict__ gg,
        const float* __restrict__ gb) {
    extern __shared__ char smem[];
    uint32_t sb = smem_to_u32(smem);
    int n0 = blockIdx.x * NTILE;
    setup_affine(smem, 0, gg, gb, ISC_OFF, ISH_OFF);
    __syncthreads();
    build_dense(smem, n0, x);
    load_A<true>(smem, w, Cc);
    __syncthreads();
    float acc[7][2][4];
    zero_acc(acc);
    mma_tile(acc, sb, B_H_OFF);
    const float* fb0 = (const float*)(smem + FB0_OFF);
    const float* fb1 = (const float*)(smem + FB1_OFF);
    int lane = threadIdx.x & 31, r0 = lane >> 2, cc0 = (lane & 3) * 2;
    int nbase = (threadIdx.x >> 5) * 16;
    float s1 = 0.f, s2 = 0.f;
    #pragma unroll
    for (int mt = 0; mt < 7; mt++)
        #pragma unroll
        for (int half = 0; half < 2; half++) {
            int m = mt * 16 + half * 8 + r0;
            float bia = __ldg(bias + m) + fb0[m] + fb1[m];
            #pragma unroll
            for (int nt = 0; nt < 2; nt++) {
                size_t gi = (size_t)m * NSP + n0 + nbase + nt * 8 + cc0;
                float o0 = acc[mt][nt][2 * half]     + bia;
                float o1 = acc[mt][nt][2 * half + 1] + bia;
                *(float2*)(g_apre + gi) = make_float2(o0, o1);
                s1 += o0 + o1; s2 += o0 * o0 + o1 * o1;
            }
        }
    write_partial8(s1, s2);
}

// ---- fused branches: s = sum_br gelu(conv2br(shift_br(A)))  (+ na2) --------
template <int BR>
__device__ __forceinline__ void branch_pass(char* smem, uint32_t sb, int n0,
                                            const float* __restrict__ w,
                                            const float* __restrict__ bias,
                                            float sum[7][2][4]) {
    __syncthreads();                 // prior mainloop done before B/A overwrite
    build_shift<BR>(smem, n0);
    load_A<false>(smem, w, Cc);
    __syncthreads();
    float acc[7][2][4];
    zero_acc(acc);
    mma_tile(acc, sb, B_H_OFF);
    int lane = threadIdx.x & 31, r0 = lane >> 2;
    #pragma unroll
    for (int mt = 0; mt < 7; mt++)
        #pragma unroll
        for (int half = 0; half < 2; half++) {
            int m = mt * 16 + half * 8 + r0;
            float bia = __ldg(bias + m);
            #pragma unroll
            for (int nt = 0; nt < 2; nt++) {
                sum[mt][nt][2 * half]     += gelu_f(acc[mt][nt][2 * half]     + bia);
                sum[mt][nt][2 * half + 1] += gelu_f(acc[mt][nt][2 * half + 1] + bia);
            }
        }
}
__global__ void __launch_bounds__(NTHR, 1)
k_branch(const float* __restrict__ wd, const float* __restrict__ bd,
         const float* __restrict__ wh, const float* __restrict__ bh,
         const float* __restrict__ ww, const float* __restrict__ bw) {
    extern __shared__ char smem[];
    uint32_t sb = smem_to_u32(smem);
    int n0 = blockIdx.x * NTILE;
    float sum[7][2][4];
    zero_acc(sum);
    branch_pass<0>(smem, sb, n0, wd, bd, sum);
    branch_pass<1>(smem, sb, n0, wh, bh, sum);
    branch_pass<2>(smem, sb, n0, ww, bw, sum);
    int lane = threadIdx.x & 31, r0 = lane >> 2, cc0 = (lane & 3) * 2;
    int nbase = (threadIdx.x >> 5) * 16;
    float s1 = 0.f, s2 = 0.f;
    #pragma unroll
    for (int mt = 0; mt < 7; mt++)
        #pragma unroll
        for (int half = 0; half < 2; half++) {
            int m = mt * 16 + half * 8 + r0;
            #pragma unroll
            for (int nt = 0; nt < 2; nt++) {
                size_t gi = (size_t)m * NSP + n0 + nbase + nt * 8 + cc0;
                float o0 = sum[mt][nt][2 * half], o1 = sum[mt][nt][2 * half + 1];
                *(float2*)(g_s + gi) = make_float2(o0, o1);
                s1 += o0 + o1; s2 += o0 * o0 + o1 * o1;
            }
        }
    write_partial8(s1, s2);
}

// ---- conv3: x1 = x + h0 + conv3_gn(s) + b'  (+ n2 partials) ----------------
__global__ void __launch_bounds__(NTHR, 2)
k_conv3(const float* __restrict__ w, const float* __restrict__ bias,
        const float* __restrict__ x, const float* __restrict__ gg,
        const float* __restrict__ gb, const float* __restrict__ n1g,
        const float* __restrict__ n1b) {
    extern __shared__ char smem[];
    uint32_t sb = smem_to_u32(smem);
    int n0 = blockIdx.x * NTILE;
    setup_affine(smem, 4, gg, gb, ISC_OFF, ISH_OFF);     // na2 on s
    setup_affine(smem, 0, n1g, n1b, HSC_OFF, HSH_OFF);   // h0 = gn_n1(x)
    __syncthreads();
    build_dense(smem, n0, g_s);
    load_A<true>(smem, w, Cc);
    __syncthreads();
    float acc[7][2][4];
    zero_acc(acc);
    mma_tile(acc, sb, B_H_OFF);
    const float* fb0 = (const float*)(smem + FB0_OFF);
    const float* fb1 = (const float*)(smem + FB1_OFF);
    const float* hsc = (const float*)(smem + HSC_OFF);
    const float* hsh = (const float*)(smem + HSH_OFF);
    int lane = threadIdx.x & 31, r0 = lane >> 2, cc0 = (lane & 3) * 2;
    int nbase = (threadIdx.x >> 5) * 16;
    float s1 = 0.f, s2 = 0.f;
    #pragma unroll
    for (int mt = 0; mt < 7; mt++)
        #pragma unroll
        for (int half = 0; half < 2; half++) {
            int m = mt * 16 + half * 8 + r0;
            float bia = __ldg(bias + m) + fb0[m] + fb1[m];
            float hc = hsc[m], hb = hsh[m];
            #pragma unroll
            for (int nt = 0; nt < 2; nt++) {
                size_t gi = (size_t)m * NSP + n0 + nbase + nt * 8 + cc0;
                float2 xv = *(const float2*)(x + gi);
                float o0 = xv.x + (xv.x * hc + hb) + acc[mt][nt][2 * half]     + bia;
                float o1 = xv.y + (xv.y * hc + hb) + acc[mt][nt][2 * half + 1] + bia;
                *(float2*)(g_x1 + gi) = make_float2(o0, o1);
                s1 += o0 + o1; s2 += o0 * o0 + o1 * o1;
            }
        }
    write_partial8(s1, s2);
}

// ---- fused MLP: out = x1 + fc2(gelu(fc1_gn(x1))) ---------------------------
__global__ void __launch_bounds__(NTHR, 1)
k_mlp(const float* __restrict__ w1, const float* __restrict__ b1,
      const float* __restrict__ w2, const float* __restrict__ b2,
      const float* __restrict__ gg, const float* __restrict__ gb,
      float* __restrict__ out) {
    extern __shared__ char smem[];
    uint32_t sb = smem_to_u32(smem);
    int n0 = blockIdx.x * NTILE;
    setup_affine(smem, 6, gg, gb, ISC_OFF, ISH_OFF);     // n2 on x1
    __syncthreads();
    build_dense(smem, n0, g_x1);                         // B1 = splitpack(x1)
    int lane = threadIdx.x & 31, r0 = lane >> 2, cc0 = (lane & 3) * 2;
    int nbase = (threadIdx.x >> 5) * 16;
    const float* fb0 = (const float*)(smem + FB0_OFF);
    const float* fb1 = (const float*)(smem + FB1_OFF);
    float acc2[7][2][4];
    zero_acc(acc2);
    #pragma unroll 1
    for (int q = 0; q < 4; q++) {
        __syncthreads();                                 // prior ml2 done
        load_A<true>(smem, w1 + (size_t)q * Cc * Cc, Cc);
        __syncthreads();
        float acc1[7][2][4];
        zero_acc(acc1);
        mma_tile(acc1, sb, B_H_OFF);
        // t = gelu(acc1 + bias') -> split-pack into B2 smem ([n][k=m] layout)
        #pragma unroll
        for (int mt = 0; mt < 7; mt++)
            #pragma unroll
            for (int half = 0; half < 2; half++) {
                int m = mt * 16 + half * 8 + r0;
                float bia = __ldg(b1 + q * Cc + m) + fb0[m] + fb1[m];
                #pragma unroll
                for (int nt = 0; nt < 2; nt++) {
                    int nn = nbase + nt * 8 + cc0;
                    uint32_t p0 = splitpack1(gelu_f(acc1[mt][nt][2 * half]     + bia));
                    uint32_t p1 = splitpack1(gelu_f(acc1[mt][nt][2 * half + 1] + bia));
                    *(uint16_t*)(smem + B2_H_OFF + nn * SROW + 2 * m)       = (uint16_t)p0;
                    *(uint16_t*)(smem + B2_H_OFF + (nn + 1) * SROW + 2 * m) = (uint16_t)p1;
                    *(uint16_t*)(smem + B2_L_OFF + nn * SROW + 2 * m)       = (uint16_t)(p0 >> 16);
                    *(uint16_t*)(smem + B2_L_OFF + (nn + 1) * SROW + 2 * m) = (uint16_t)(p1 >> 16);
                }
            }
        __syncthreads();                                 // t-writes visible; ml1 done
        load_A<false>(smem, w2 + q * Cc, HID);           // fc2 chunk columns
        __syncthreads();
        mma_tile(acc2, sb, B2_H_OFF);
    }
    #pragma unroll
    for (int mt = 0; mt < 7; mt++)
        #pragma unroll
        for (int half = 0; half < 2; half++) {
            int m = mt * 16 + half * 8 + r0;
            float bia = __ldg(b2 + m);
            #pragma unroll
            for (int nt = 0; nt < 2; nt++) {
                size_t gi = (size_t)m * NSP + n0 + nbase + nt * 8 + cc0;
                float2 xv = *(const float2*)(g_x1 + gi);
                *(float2*)(out + gi) =
                    make_float2(xv.x + acc2[mt][nt][2 * half]     + bia,
                                xv.y + acc2[mt][nt][2 * half + 1] + bia);
            }
        }
}

// ---------------- launch -----------------------------------------------------
extern "C" void kernel_launch(void* const* d_in, const int* in_sizes, int n_in,
                              void* d_out, int out_size) {
    const float* x        = (const float*)d_in[0];
    const float* conv1_w  = (const float*)d_in[1];
    const float* conv1_b  = (const float*)d_in[2];
    const float* conv2d_w = (const float*)d_in[3];
    const float* conv2d_b = (const float*)d_in[4];
    const float* conv2h_w = (const float*)d_in[5];
    const float* conv2h_b = (const float*)d_in[6];
    const float* conv2w_w = (const float*)d_in[7];
    const float* conv2w_b = (const float*)d_in[8];
    const float* conv3_w  = (const float*)d_in[9];
    const float* conv3_b  = (const float*)d_in[10];
    const float* fc1_w    = (const float*)d_in[11];
    const float* fc1_b    = (const float*)d_in[12];
    const float* fc2_w    = (const float*)d_in[13];
    const float* fc2_b    = (const float*)d_in[14];
    const float* n1_g     = (const float*)d_in[15];
    const float* n1_b     = (const float*)d_in[16];
    const float* na1_g    = (const float*)d_in[17];
    const float* na1_b    = (const float*)d_in[18];
    const float* na2_g    = (const float*)d_in[19];
    const float* na2_b    = (const float*)d_in[20];
    const float* n2_g     = (const float*)d_in[21];
    const float* n2_b     = (const float*)d_in[22];
    float* out = (float*)d_out;

    cudaFuncSetAttribute(k_conv1,  cudaFuncAttributeMaxDynamicSharedMemorySize, SM_CONV);
    cudaFuncSetAttribute(k_branch, cudaFuncAttributeMaxDynamicSharedMemorySize, SM_CONV);
    cudaFuncSetAttribute(k_conv3,  cudaFuncAttributeMaxDynamicSharedMemorySize, SM_CONV);
    cudaFuncSetAttribute(k_mlp,    cudaFuncAttributeMaxDynamicSharedMemorySize, SM_MLP);

    k_stats<<<1024, NTHR>>>(x);
    k_reduce<<<1, NTHR>>>(1024, 0);
    k_conv1<<<NT2, NTHR, SM_CONV>>>(conv1_w, conv1_b, x, n1_g, n1_b);
    k_reduce<<<1, NTHR>>>(NT2, 2);
    k_gngelu<<<2048, NTHR>>>(na1_g, na1_b);
    k_branch<<<NT2, NTHR, SM_CONV>>>(conv2d_w, conv2d_b, conv2h_w, conv2h_b,
                                     conv2w_w, conv2w_b);
    k_reduce<<<1, NTHR>>>(NT2, 4);
    k_conv3<<<NT2, NTHR, SM_CONV>>>(conv3_w, conv3_b, x, na2_g, na2_b, n1_g, n1_b);
    k_reduce<<<1, NTHR>>>(NT2, 6);
    k_mlp<<<NT2, NTHR, SM_MLP>>>(fc1_w, fc1_b, fc2_w, fc2_b, n2_g, n2_b, out);
}

// round 12
// speedup vs baseline: 2.1454x; 1.0534x over previous
#include <cuda_runtime.h>
#include <cuda_fp16.h>
#include <cstdint>

// ---------------------------------------------------------------------------
// CoalUMLP block, C=112, 64^3, B=1 — HMMA fp16 2-pass split version.
//   R10 -> R12: split scheme bf16 3-pass -> fp16 2-pass (weights split hi/lo
//   fp16, inputs single-rounded fp16; input-rounding error ~2^-12). Cuts MMA
//   count 33%, halves B smem (single buffer) and activation cache traffic.
// Pipeline (10 launches):
//   k_stats/k_reduce -> n1 stats
//   k_conv1: a_pre = conv1_gn(x)            -> na1 partials
//   k_gngelu: Ah = fp16(gelu(gn(a_pre)))
//   k_branch: s = sum_br gelu(conv2br(shift_br(Ah)))  -> na2 partials
//   k_conv3: x1 = x + h0 + conv3_gn(s)      -> n2 partials
//   k_mlp:   out = x1 + fc2(gelu(fc1_gn(x1)))
// ---------------------------------------------------------------------------

#define Cc      112
#define NSP     262144
#define NTOTAL  (Cc*NSP)
#define HID     448
#define EPSF    1e-5
#define NTILE   128
#define NT2     (NSP/NTILE)          // 2048
#define KSTEPS  7
#define NTHR    256
#define SROW    224                  // 112 fp16 = 224B rows; LDSM-conflict-free

// smem byte offsets
#define ISC_OFF 0
#define ISH_OFF 512
#define FB0_OFF 1024
#define FB1_OFF 1536
#define HSC_OFF 2048
#define HSH_OFF 2560
#define A_H_OFF 3072
#define A_L_OFF (A_H_OFF + Cc*SROW)      // 28160
#define B_OFF   (A_L_OFF + Cc*SROW)      // 53248
#define SM_CONV (B_OFF + NTILE*SROW)     // 81920 (80KB) -> 2 CTA/SM
#define B2_OFF  SM_CONV                  // mlp t-buffer
#define SM_MLP  (B2_OFF + NTILE*SROW)    // 110592 (108KB)

// ---- device scratch ---------------------------------------------------------
__device__ float    g_apre[NTOTAL];
__device__ uint16_t g_Ah[NTOTAL];        // fp16(gelu(gn(a_pre)))
__device__ float    g_s[NTOTAL];
__device__ float    g_x1[NTOTAL];
__device__ float2   g_part[NT2];
__device__ double   g_stats[8];          // [0,1]=x [2,3]=a_pre [4,5]=s [6,7]=x1

// ---- PTX helpers ------------------------------------------------------------
__device__ __forceinline__ uint32_t smem_to_u32(const void* p) {
    uint32_t a;
    asm("{ .reg .u64 t; cvta.to.shared.u64 t, %1; cvt.u32.u64 %0, t; }"
        : "=r"(a) : "l"(p));
    return a;
}
__device__ __forceinline__ void ldsm4(uint32_t* r, uint32_t addr) {
    asm volatile("ldmatrix.sync.aligned.m8n8.x4.shared.b16 {%0,%1,%2,%3}, [%4];"
        : "=r"(r[0]), "=r"(r[1]), "=r"(r[2]), "=r"(r[3]) : "r"(addr));
}
__device__ __forceinline__ void mma16816(float* c, const uint32_t* a,
                                         const uint32_t* b) {
    asm volatile("mma.sync.aligned.m16n8k16.row.col.f32.f16.f16.f32 "
        "{%0,%1,%2,%3}, {%4,%5,%6,%7}, {%8,%9}, {%0,%1,%2,%3};"
        : "+f"(c[0]), "+f"(c[1]), "+f"(c[2]), "+f"(c[3])
        : "r"(a[0]), "r"(a[1]), "r"(a[2]), "r"(a[3]), "r"(b[0]), "r"(b[1]));
}

// ---- math helpers -----------------------------------------------------------
__device__ __forceinline__ float gelu_f(float x) {
    return 0.5f * x * (1.0f + erff(x * 0.70710678118654752440f));
}
__device__ __forceinline__ float2 gn_musig(int idx) {
    double mu  = g_stats[idx] * (1.0 / (double)NTOTAL);
    double var = g_stats[idx + 1] * (1.0 / (double)NTOTAL) - mu * mu;
    float  rs  = (float)(1.0 / sqrt(var + (double)EPSF));
    return make_float2((float)mu, rs);
}
__device__ __forceinline__ uint16_t f2h(float v) {
    return __half_as_ushort(__float2half_rn(v));
}
__device__ __forceinline__ uint32_t packh(float v0, float v1) {
    return (uint32_t)f2h(v0) | ((uint32_t)f2h(v1) << 16);
}
// weight split: hi = fp16(v), lo = fp16(v - hi)
__device__ __forceinline__ uint32_t split_pairh(float v0, float v1, uint32_t& lo) {
    __half h0 = __float2half_rn(v0), h1 = __float2half_rn(v1);
    lo = packh(v0 - __half2float(h0), v1 - __half2float(h1));
    return (uint32_t)__half_as_ushort(h0) | ((uint32_t)__half_as_ushort(h1) << 16);
}
__device__ __forceinline__ void write_partial8(float s1, float s2) {
    __shared__ float r1[8], r2[8];
    #pragma unroll
    for (int o = 16; o; o >>= 1) {
        s1 += __shfl_down_sync(0xffffffffu, s1, o);
        s2 += __shfl_down_sync(0xffffffffu, s2, o);
    }
    int wid = threadIdx.x >> 5, lane = threadIdx.x & 31;
    if (!lane) { r1[wid] = s1; r2[wid] = s2; }
    __syncthreads();
    if (!threadIdx.x) {
        float a = 0.f, b = 0.f;
        #pragma unroll
        for (int i = 0; i < 8; i++) { a += r1[i]; b += r2[i]; }
        g_part[blockIdx.x] = make_float2(a, b);
    }
}

// ---- small elementwise kernels ---------------------------------------------
__global__ void k_stats(const float* __restrict__ x) {
    float s1 = 0.f, s2 = 0.f;
    for (int i = (blockIdx.x * NTHR + threadIdx.x) * 4; i < NTOTAL;
         i += gridDim.x * NTHR * 4) {
        float4 v = *(const float4*)(x + i);
        s1 += v.x + v.y + v.z + v.w;
        s2 += v.x * v.x + v.y * v.y + v.z * v.z + v.w * v.w;
    }
    write_partial8(s1, s2);
}
__global__ void k_reduce(int n, int outIdx) {
    __shared__ double d1[NTHR], d2[NTHR];
    double a = 0.0, b = 0.0;
    for (int i = threadIdx.x; i < n; i += NTHR) {
        a += (double)g_part[i].x; b += (double)g_part[i].y;
    }
    d1[threadIdx.x] = a; d2[threadIdx.x] = b;
    __syncthreads();
    for (int s = NTHR / 2; s; s >>= 1) {
        if (threadIdx.x < s) {
            d1[threadIdx.x] += d1[threadIdx.x + s];
            d2[threadIdx.x] += d2[threadIdx.x + s];
        }
        __syncthreads();
    }
    if (!threadIdx.x) { g_stats[outIdx] = d1[0]; g_stats[outIdx + 1] = d2[0]; }
}
// g_Ah = fp16(gelu(gn_na1(g_apre)))
__global__ void k_gngelu(const float* __restrict__ gg, const float* __restrict__ gb) {
    float2 ms = gn_musig(2);
    for (int i = (blockIdx.x * NTHR + threadIdx.x) * 8; i < NTOTAL;
         i += gridDim.x * NTHR * 8) {
        int   c  = i >> 18;
        float gv = __ldg(gg + c);
        float sc = ms.y * gv;
        float sh = __ldg(gb + c) - ms.x * sc;
        float4 v0 = *(const float4*)(g_apre + i);
        float4 v1 = *(const float4*)(g_apre + i + 4);
        uint4 o;
        o.x = packh(gelu_f(v0.x * sc + sh), gelu_f(v0.y * sc + sh));
        o.y = packh(gelu_f(v0.z * sc + sh), gelu_f(v0.w * sc + sh));
        o.z = packh(gelu_f(v1.x * sc + sh), gelu_f(v1.y * sc + sh));
        o.w = packh(gelu_f(v1.z * sc + sh), gelu_f(v1.w * sc + sh));
        *(uint4*)(g_Ah + i) = o;
    }
}

// ---- axial-shift gather -----------------------------------------------------
template <int BR>
__device__ __forceinline__ uint32_t fetch_shift(int k, int d, int h, int wq) {
    int sk = (k >> 4) - 3, dd, hh, ww;
    if (BR == 0)      { dd = d - sk; hh = h;          ww = wq; }
    else if (BR == 1) { dd = d - 3;  hh = h - sk - 3; ww = wq - 3; }
    else              { dd = d - 6;  hh = h - 6;      ww = wq - sk - 6; }
    bool ok = ((unsigned)dd < 64u) & ((unsigned)hh < 64u) & ((unsigned)ww < 64u);
    return ok ? (uint32_t)g_Ah[(size_t)k * NSP + (dd << 12) + (hh << 6) + ww] : 0u;
}

// ---- B tile build (single fp16) --------------------------------------------
// 256 threads: t&127 = n-row, t>>7 = k-half (56 k's each)
__device__ __forceinline__ void build_dense(char* smem, int bOff, int n0,
                                            const float* __restrict__ sp) {
    int t7 = threadIdx.x & 127, kh = threadIdx.x >> 7;
    int n = n0 + t7;
    char* bp = smem + bOff + t7 * SROW;
    #pragma unroll 1
    for (int i = 0; i < 7; i++) {
        int k0 = kh * 56 + i * 8;
        uint32_t hv[4];
        #pragma unroll
        for (int j = 0; j < 4; j++) {
            int k = k0 + 2 * j;
            hv[j] = packh(__ldg(sp + (size_t)k * NSP + n),
                          __ldg(sp + (size_t)(k + 1) * NSP + n));
        }
        *(uint4*)(bp + 2 * k0) = make_uint4(hv[0], hv[1], hv[2], hv[3]);
    }
}
template <int BR>
__device__ __forceinline__ void build_shift(char* smem, int n0) {
    int t7 = threadIdx.x & 127, kh = threadIdx.x >> 7;
    int n = n0 + t7;
    int d = n >> 12, h = (n >> 6) & 63, wq = n & 63;
    char* bp = smem + B_OFF + t7 * SROW;
    #pragma unroll 1
    for (int i = 0; i < 7; i++) {
        int k0 = kh * 56 + i * 8;
        uint32_t hv[4];
        #pragma unroll
        for (int j = 0; j < 4; j++) {
            int k = k0 + 2 * j;
            hv[j] = fetch_shift<BR>(k, d, h, wq)
                  | (fetch_shift<BR>(k + 1, d, h, wq) << 16);
        }
        *(uint4*)(bp + 2 * k0) = make_uint4(hv[0], hv[1], hv[2], hv[3]);
    }
}

// ---- weights -> smem A hi/lo (optionally GN-folded) ------------------------
// 224 threads: t>>1 = row, t&1 = k-half
template <bool FOLD>
__device__ __forceinline__ void load_A(char* smem, const float* __restrict__ wsrc,
                                       int rstride) {
    int t = threadIdx.x;
    if (t < 224) {
        int r = t >> 1, h = t & 1;
        const float* row = wsrc + (size_t)r * rstride + h * 56;
        const float* isc = (const float*)(smem + ISC_OFF);
        const float* ish = (const float*)(smem + ISH_OFF);
        char* ah = smem + A_H_OFF + r * SROW + h * 112;
        char* al = smem + A_L_OFF + r * SROW + h * 112;
        float part = 0.f;
        #pragma unroll
        for (int i = 0; i < 7; i++) {
            int kb = h * 56 + i * 8;
            float4 v0 = __ldg((const float4*)(row + i * 8));
            float4 v1 = __ldg((const float4*)(row + i * 8 + 4));
            if (FOLD) {
                part += v0.x * ish[kb] + v0.y * ish[kb + 1] + v0.z * ish[kb + 2]
                      + v0.w * ish[kb + 3] + v1.x * ish[kb + 4] + v1.y * ish[kb + 5]
                      + v1.z * ish[kb + 6] + v1.w * ish[kb + 7];
                v0.x *= isc[kb];     v0.y *= isc[kb + 1];
                v0.z *= isc[kb + 2]; v0.w *= isc[kb + 3];
                v1.x *= isc[kb + 4]; v1.y *= isc[kb + 5];
                v1.z *= isc[kb + 6]; v1.w *= isc[kb + 7];
            }
            uint4 hv, lv;
            hv.x = split_pairh(v0.x, v0.y, lv.x);
            hv.y = split_pairh(v0.z, v0.w, lv.y);
            hv.z = split_pairh(v1.x, v1.y, lv.z);
            hv.w = split_pairh(v1.z, v1.w, lv.w);
            *(uint4*)(ah + i * 16) = hv;
            *(uint4*)(al + i * 16) = lv;
        }
        if (FOLD)
            ((float*)(smem + (h ? FB1_OFF : FB0_OFF)))[r] = part;
    }
}

// ---- GN affine setup --------------------------------------------------------
__device__ __forceinline__ void setup_affine(char* smem, int statIdx,
                                             const float* gg, const float* gb,
                                             int scOff, int shOff) {
    float2 ms = gn_musig(statIdx);
    for (int i = threadIdx.x; i < Cc; i += NTHR) {
        float g = __ldg(gg + i);
        ((float*)(smem + scOff))[i] = ms.y * g;
        ((float*)(smem + shOff))[i] = __ldg(gb + i) - ms.x * ms.y * g;
    }
}

// ---- MMA mainloop: acc[7][2][4] += 2-pass split product --------------------
__device__ __forceinline__ void mma_tile(float acc[7][2][4], uint32_t sb,
                                         uint32_t bOff) {
    int lane = threadIdx.x & 31;
    int nbase = (threadIdx.x >> 5) * 16;
    uint32_t aAddr = sb + A_H_OFF + (uint32_t)(lane & 15) * SROW
                     + (uint32_t)(lane >> 4) * 16;
    uint32_t bAddr = sb + bOff
                   + (uint32_t)(nbase + ((lane >> 4) << 3) + (lane & 7)) * SROW
                   + (uint32_t)((lane >> 3) & 1) * 16;
    const uint32_t dA = A_L_OFF - A_H_OFF;
    #pragma unroll
    for (int ks = 0; ks < KSTEPS; ks++) {
        uint32_t bv[4];
        ldsm4(bv, bAddr + ks * 32);
        #pragma unroll
        for (int mt = 0; mt < 7; mt++) {
            uint32_t ah[4], al[4];
            ldsm4(ah, aAddr + mt * 16 * SROW + ks * 32);
            ldsm4(al, aAddr + dA + mt * 16 * SROW + ks * 32);
            #pragma unroll
            for (int nt = 0; nt < 2; nt++) {
                mma16816(acc[mt][nt], ah, bv + 2 * nt);
                mma16816(acc[mt][nt], al, bv + 2 * nt);
            }
        }
    }
}
__device__ __forceinline__ void zero_acc(float acc[7][2][4]) {
    #pragma unroll
    for (int a = 0; a < 7; a++)
        #pragma unroll
        for (int b = 0; b < 2; b++)
            #pragma unroll
            for (int u = 0; u < 4; u++) acc[a][b][u] = 0.f;
}

// ---- conv1 ------------------------------------------------------------------
__global__ void __launch_bounds__(NTHR, 2)
k_conv1(const float* __restrict__ w, const float* __restrict__ bias,
        const float* __restrict__ x, const float* __restrict__ gg,
        const float* __restrict__ gb) {
    extern __shared__ char smem[];
    uint32_t sb = smem_to_u32(smem);
    int n0 = blockIdx.x * NTILE;
    setup_affine(smem, 0, gg, gb, ISC_OFF, ISH_OFF);
    __syncthreads();
    build_dense(smem, B_OFF, n0, x);
    load_A<true>(smem, w, Cc);
    __syncthreads();
    float acc[7][2][4];
    zero_acc(acc);
    mma_tile(acc, sb, B_OFF);
    const float* fb0 = (const float*)(smem + FB0_OFF);
    const float* fb1 = (const float*)(smem + FB1_OFF);
    int lane = threadIdx.x & 31, r0 = lane >> 2, cc0 = (lane & 3) * 2;
    int nbase = (threadIdx.x >> 5) * 16;
    float s1 = 0.f, s2 = 0.f;
    #pragma unroll
    for (int mt = 0; mt < 7; mt++)
        #pragma unroll
        for (int half = 0; half < 2; half++) {
            int m = mt * 16 + half * 8 + r0;
            float bia = __ldg(bias + m) + fb0[m] + fb1[m];
            #pragma unroll
            for (int nt = 0; nt < 2; nt++) {
                size_t gi = (size_t)m * NSP + n0 + nbase + nt * 8 + cc0;
                float o0 = acc[mt][nt][2 * half]     + bia;
                float o1 = acc[mt][nt][2 * half + 1] + bia;
                *(float2*)(g_apre + gi) = make_float2(o0, o1);
                s1 += o0 + o1; s2 += o0 * o0 + o1 * o1;
            }
        }
    write_partial8(s1, s2);
}

// ---- fused branches ---------------------------------------------------------
template <int BR>
__device__ __forceinline__ void branch_pass(char* smem, uint32_t sb, int n0,
                                            const float* __restrict__ w,
                                            const float* __restrict__ bias,
                                            float sum[7][2][4]) {
    __syncthreads();
    build_shift<BR>(smem, n0);
    load_A<false>(smem, w, Cc);
    __syncthreads();
    float acc[7][2][4];
    zero_acc(acc);
    mma_tile(acc, sb, B_OFF);
    int lane = threadIdx.x & 31, r0 = lane >> 2;
    #pragma unroll
    for (int mt = 0; mt < 7; mt++)
        #pragma unroll
        for (int half = 0; half < 2; half++) {
            int m = mt * 16 + half * 8 + r0;
            float bia = __ldg(bias + m);
            #pragma unroll
            for (int nt = 0; nt < 2; nt++) {
                sum[mt][nt][2 * half]     += gelu_f(acc[mt][nt][2 * half]     + bia);
                sum[mt][nt][2 * half + 1] += gelu_f(acc[mt][nt][2 * half + 1] + bia);
            }
        }
}
__global__ void __launch_bounds__(NTHR, 1)
k_branch(const float* __restrict__ wd, const float* __restrict__ bd,
         const float* __restrict__ wh, const float* __restrict__ bh,
         const float* __restrict__ ww, const float* __restrict__ bw) {
    extern __shared__ char smem[];
    uint32_t sb = smem_to_u32(smem);
    int n0 = blockIdx.x * NTILE;
    float sum[7][2][4];
    zero_acc(sum);
    branch_pass<0>(smem, sb, n0, wd, bd, sum);
    branch_pass<1>(smem, sb, n0, wh, bh, sum);
    branch_pass<2>(smem, sb, n0, ww, bw, sum);
    int lane = threadIdx.x & 31, r0 = lane >> 2, cc0 = (lane & 3) * 2;
    int nbase = (threadIdx.x >> 5) * 16;
    float s1 = 0.f, s2 = 0.f;
    #pragma unroll
    for (int mt = 0; mt < 7; mt++)
        #pragma unroll
        for (int half = 0; half < 2; half++) {
            int m = mt * 16 + half * 8 + r0;
            #pragma unroll
            for (int nt = 0; nt < 2; nt++) {
                size_t gi = (size_t)m * NSP + n0 + nbase + nt * 8 + cc0;
                float o0 = sum[mt][nt][2 * half], o1 = sum[mt][nt][2 * half + 1];
                *(float2*)(g_s + gi) = make_float2(o0, o1);
                s1 += o0 + o1; s2 += o0 * o0 + o1 * o1;
            }
        }
    write_partial8(s1, s2);
}

// ---- conv3 ------------------------------------------------------------------
__global__ void __launch_bounds__(NTHR, 2)
k_conv3(const float* __restrict__ w, const float* __restrict__ bias,
        const float* __restrict__ x, const float* __restrict__ gg,
        const float* __restrict__ gb, const float* __restrict__ n1g,
        const float* __restrict__ n1b) {
    extern __shared__ char smem[];
    uint32_t sb = smem_to_u32(smem);
    int n0 = blockIdx.x * NTILE;
    setup_affine(smem, 4, gg, gb, ISC_OFF, ISH_OFF);     // na2 on s
    setup_affine(smem, 0, n1g, n1b, HSC_OFF, HSH_OFF);   // h0 = gn_n1(x)
    __syncthreads();
    build_dense(smem, B_OFF, n0, g_s);
    load_A<true>(smem, w, Cc);
    __syncthreads();
    float acc[7][2][4];
    zero_acc(acc);
    mma_tile(acc, sb, B_OFF);
    const float* fb0 = (const float*)(smem + FB0_OFF);
    const float* fb1 = (const float*)(smem + FB1_OFF);
    const float* hsc = (const float*)(smem + HSC_OFF);
    const float* hsh = (const float*)(smem + HSH_OFF);
    int lane = threadIdx.x & 31, r0 = lane >> 2, cc0 = (lane & 3) * 2;
    int nbase = (threadIdx.x >> 5) * 16;
    float s1 = 0.f, s2 = 0.f;
    #pragma unroll
    for (int mt = 0; mt < 7; mt++)
        #pragma unroll
        for (int half = 0; half < 2; half++) {
            int m = mt * 16 + half * 8 + r0;
            float bia = __ldg(bias + m) + fb0[m] + fb1[m];
            float hc = hsc[m], hb = hsh[m];
            #pragma unroll
            for (int nt = 0; nt < 2; nt++) {
                size_t gi = (size_t)m * NSP + n0 + nbase + nt * 8 + cc0;
                float2 xv = *(const float2*)(x + gi);
                float o0 = xv.x + (xv.x * hc + hb) + acc[mt][nt][2 * half]     + bia;
                float o1 = xv.y + (xv.y * hc + hb) + acc[mt][nt][2 * half + 1] + bia;
                *(float2*)(g_x1 + gi) = make_float2(o0, o1);
                s1 += o0 + o1; s2 += o0 * o0 + o1 * o1;
            }
        }
    write_partial8(s1, s2);
}

// ---- fused MLP --------------------------------------------------------------
__global__ void __launch_bounds__(NTHR, 1)
k_mlp(const float* __restrict__ w1, const float* __restrict__ b1,
      const float* __restrict__ w2, const float* __restrict__ b2,
      const float* __restrict__ gg, const float* __restrict__ gb,
      float* __restrict__ out) {
    extern __shared__ char smem[];
    uint32_t sb = smem_to_u32(smem);
    int n0 = blockIdx.x * NTILE;
    setup_affine(smem, 6, gg, gb, ISC_OFF, ISH_OFF);     // n2 on x1
    __syncthreads();
    build_dense(smem, B_OFF, n0, g_x1);
    int lane = threadIdx.x & 31, r0 = lane >> 2, cc0 = (lane & 3) * 2;
    int nbase = (threadIdx.x >> 5) * 16;
    const float* fb0 = (const float*)(smem + FB0_OFF);
    const float* fb1 = (const float*)(smem + FB1_OFF);
    float acc2[7][2][4];
    zero_acc(acc2);
    #pragma unroll 1
    for (int q = 0; q < 4; q++) {
        __syncthreads();
        load_A<true>(smem, w1 + (size_t)q * Cc * Cc, Cc);
        __syncthreads();
        float acc1[7][2][4];
        zero_acc(acc1);
        mma_tile(acc1, sb, B_OFF);
        // t = fp16(gelu(acc1 + bias')) -> B2 smem ([n][k=m] layout)
        #pragma unroll
        for (int mt = 0; mt < 7; mt++)
            #pragma unroll
            for (int half = 0; half < 2; half++) {
                int m = mt * 16 + half * 8 + r0;
                float bia = __ldg(b1 + q * Cc + m) + fb0[m] + fb1[m];
                #pragma unroll
                for (int nt = 0; nt < 2; nt++) {
                    int nn = nbase + nt * 8 + cc0;
                    *(uint16_t*)(smem + B2_OFF + nn * SROW + 2 * m) =
                        f2h(gelu_f(acc1[mt][nt][2 * half] + bia));
                    *(uint16_t*)(smem + B2_OFF + (nn + 1) * SROW + 2 * m) =
                        f2h(gelu_f(acc1[mt][nt][2 * half + 1] + bia));
                }
            }
        __syncthreads();
        load_A<false>(smem, w2 + q * Cc, HID);
        __syncthreads();
        mma_tile(acc2, sb, B2_OFF);
    }
    #pragma unroll
    for (int mt = 0; mt < 7; mt++)
        #pragma unroll
        for (int half = 0; half < 2; half++) {
            int m = mt * 16 + half * 8 + r0;
            float bia = __ldg(b2 + m);
            #pragma unroll
            for (int nt = 0; nt < 2; nt++) {
                size_t gi = (size_t)m * NSP + n0 + nbase + nt * 8 + cc0;
                float2 xv = *(const float2*)(g_x1 + gi);
                *(float2*)(out + gi) =
                    make_float2(xv.x + acc2[mt][nt][2 * half]     + bia,
                                xv.y + acc2[mt][nt][2 * half + 1] + bia);
            }
        }
}

// ---------------- launch -----------------------------------------------------
extern "C" void kernel_launch(void* const* d_in, const int* in_sizes, int n_in,
                              void* d_out, int out_size) {
    const float* x        = (const float*)d_in[0];
    const float* conv1_w  = (const float*)d_in[1];
    const float* conv1_b  = (const float*)d_in[2];
    const float* conv2d_w = (const float*)d_in[3];
    const float* conv2d_b = (const float*)d_in[4];
    const float* conv2h_w = (const float*)d_in[5];
    const float* conv2h_b = (const float*)d_in[6];
    const float* conv2w_w = (const float*)d_in[7];
    const float* conv2w_b = (const float*)d_in[8];
    const float* conv3_w  = (const float*)d_in[9];
    const float* conv3_b  = (const float*)d_in[10];
    const float* fc1_w    = (const float*)d_in[11];
    const float* fc1_b    = (const float*)d_in[12];
    const float* fc2_w    = (const float*)d_in[13];
    const float* fc2_b    = (const float*)d_in[14];
    const float* n1_g     = (const float*)d_in[15];
    const float* n1_b     = (const float*)d_in[16];
    const float* na1_g    = (const float*)d_in[17];
    const float* na1_b    = (const float*)d_in[18];
    const float* na2_g    = (const float*)d_in[19];
    const float* na2_b    = (const float*)d_in[20];
    const float* n2_g     = (const float*)d_in[21];
    const float* n2_b     = (const float*)d_in[22];
    float* out = (float*)d_out;

    cudaFuncSetAttribute(k_conv1,  cudaFuncAttributeMaxDynamicSharedMemorySize, SM_CONV);
    cudaFuncSetAttribute(k_branch, cudaFuncAttributeMaxDynamicSharedMemorySize, SM_CONV);
    cudaFuncSetAttribute(k_conv3,  cudaFuncAttributeMaxDynamicSharedMemorySize, SM_CONV);
    cudaFuncSetAttribute(k_mlp,    cudaFuncAttributeMaxDynamicSharedMemorySize, SM_MLP);

    k_stats<<<1024, NTHR>>>(x);
    k_reduce<<<1, NTHR>>>(1024, 0);
    k_conv1<<<NT2, NTHR, SM_CONV>>>(conv1_w, conv1_b, x, n1_g, n1_b);
    k_reduce<<<1, NTHR>>>(NT2, 2);
    k_gngelu<<<2048, NTHR>>>(na1_g, na1_b);
    k_branch<<<NT2, NTHR, SM_CONV>>>(conv2d_w, conv2d_b, conv2h_w, conv2h_b,
                                     conv2w_w, conv2w_b);
    k_reduce<<<1, NTHR>>>(NT2, 4);
    k_conv3<<<NT2, NTHR, SM_CONV>>>(conv3_w, conv3_b, x, na2_g, na2_b, n1_g, n1_b);
    k_reduce<<<1, NTHR>>>(NT2, 6);
    k_mlp<<<NT2, NTHR, SM_MLP>>>(fc1_w, fc1_b, fc2_w, fc2_b, n2_g, n2_b, out);
}